// round 1
// baseline (speedup 1.0000x reference)
#include <cuda_runtime.h>
#include <math.h>

// Problem constants
static constexpr int B_ = 4, S_ = 1024, D_ = 512, H_ = 8, F_ = 2048, DH_ = 64, L_ = 8;
static constexpr int M_ROWS = B_ * S_;           // 4096
static constexpr float QK_SCALE = 0.125f;        // 1/sqrt(64)
static constexpr float LN_EPS = 1e-5f;

// Scratch (device globals; no allocation in kernel_launch)
__device__ float g_x[M_ROWS * D_];
__device__ float g_q[M_ROWS * D_];
__device__ float g_kk[M_ROWS * D_];
__device__ float g_vv[M_ROWS * D_];
__device__ float g_attn[M_ROWS * D_];
__device__ float g_tmp[M_ROWS * D_];
__device__ float g_ffn[M_ROWS * F_];
__device__ float g_sc[(size_t)B_ * H_ * S_ * S_];   // 134 MB

enum { M_HEADS = 1, M_RES = 2, M_GELU = 3, M_SCORES = 4, M_PV = 5 };

// ---------------------------------------------------------------------------
// Generic register-blocked SGEMM with compile-time epilogue.
// C(z)[m,n] = sum_k A(z)[m,k] * B(z)[k,n]  (TRANSB: B(z)[n,k])
// ---------------------------------------------------------------------------
template <int BM, int BN, int BK, int TM, int TN, bool TRANSB, int MODE>
__global__ __launch_bounds__((BM / TM) * (BN / TN))
void gemm_k(const float* __restrict__ A, const float* __restrict__ Bm,
            const float* __restrict__ bias, const float* __restrict__ res,
            float* __restrict__ C, int M, int N, int K, int lda, int ldb,
            long sA, long sB, long sC, float alpha)
{
    constexpr int THREADS = (BM / TM) * (BN / TN);
    __shared__ float As[BK][BM];
    __shared__ float Bs[BK][BN];

    const int z = blockIdx.z;
    A  += (long)z * sA;
    Bm += (long)z * sB;
    C  += (long)z * sC;

    const int bm = blockIdx.y * BM;
    const int bn = blockIdx.x * BN;
    const int tid = threadIdx.x;
    const int tx = tid % (BN / TN);
    const int ty = tid / (BN / TN);

    float acc[TM][TN] = {};

    for (int k0 = 0; k0 < K; k0 += BK) {
        // Load A tile (row-major, vectorize along K), store transposed As[k][m]
        for (int i = tid * 4; i < BM * BK; i += THREADS * 4) {
            int r = i / BK, c = i % BK;
            float4 v = *reinterpret_cast<const float4*>(A + (long)(bm + r) * lda + k0 + c);
            As[c + 0][r] = v.x; As[c + 1][r] = v.y;
            As[c + 2][r] = v.z; As[c + 3][r] = v.w;
        }
        if (TRANSB) {
            // B[n,k]: vectorize along K, scatter into Bs[k][n]
            for (int i = tid * 4; i < BN * BK; i += THREADS * 4) {
                int r = i / BK, c = i % BK;
                float4 v = *reinterpret_cast<const float4*>(Bm + (long)(bn + r) * ldb + k0 + c);
                Bs[c + 0][r] = v.x; Bs[c + 1][r] = v.y;
                Bs[c + 2][r] = v.z; Bs[c + 3][r] = v.w;
            }
        } else {
            // B[k,n]: vectorize along N
            for (int i = tid * 4; i < BK * BN; i += THREADS * 4) {
                int r = i / BN, c = i % BN;
                *reinterpret_cast<float4*>(&Bs[r][c]) =
                    *reinterpret_cast<const float4*>(Bm + (long)(k0 + r) * ldb + bn + c);
            }
        }
        __syncthreads();

        #pragma unroll
        for (int kk = 0; kk < BK; kk++) {
            float ra[TM], rb[TN];
            #pragma unroll
            for (int i = 0; i < TM; i += 4)
                *reinterpret_cast<float4*>(&ra[i]) =
                    *reinterpret_cast<const float4*>(&As[kk][ty * TM + i]);
            #pragma unroll
            for (int j = 0; j < TN; j += 4)
                *reinterpret_cast<float4*>(&rb[j]) =
                    *reinterpret_cast<const float4*>(&Bs[kk][tx * TN + j]);
            #pragma unroll
            for (int i = 0; i < TM; i++)
                #pragma unroll
                for (int j = 0; j < TN; j++)
                    acc[i][j] = fmaf(ra[i], rb[j], acc[i][j]);
        }
        __syncthreads();
    }

    // Epilogue
    #pragma unroll
    for (int i = 0; i < TM; i++) {
        const int m = bm + ty * TM + i;
        #pragma unroll
        for (int j = 0; j < TN; j++) {
            const int n = bn + tx * TN + j;
            float v = acc[i][j];
            if (MODE == M_HEADS) {
                v = (v + bias[n]) * alpha;
                int b = m >> 10, s = m & 1023, h = n >> 6, dh = n & 63;
                C[(((long)(b * H_ + h) * S_ + s) << 6) + dh] = v;
            } else if (MODE == M_RES) {
                C[(long)m * N + n] = v + bias[n] + res[(long)m * N + n];
            } else if (MODE == M_GELU) {
                v += bias[n];
                C[(long)m * N + n] = 0.5f * v * (1.0f + erff(v * 0.70710678118654752f));
            } else if (MODE == M_SCORES) {
                C[(long)m * N + n] = v;
            } else { // M_PV: z = b*H + h, write [B,S,D] layout
                int b = z >> 3, h = z & 7;
                C[((long)(b * S_ + m)) * D_ + h * DH_ + n] = v;
            }
        }
    }
}

// ---------------------------------------------------------------------------
// Row softmax over 1024 elements, in place. grid = B*H*S rows, 256 threads.
// ---------------------------------------------------------------------------
__global__ __launch_bounds__(256) void softmax_k(float* __restrict__ Sc)
{
    const size_t row = blockIdx.x;
    float4* p = reinterpret_cast<float4*>(Sc + row * (size_t)S_);
    const int t = threadIdx.x;
    float4 v = p[t];

    float m = fmaxf(fmaxf(v.x, v.y), fmaxf(v.z, v.w));
    __shared__ float shm[8];
    #pragma unroll
    for (int o = 16; o; o >>= 1) m = fmaxf(m, __shfl_xor_sync(0xFFFFFFFFu, m, o));
    if ((t & 31) == 0) shm[t >> 5] = m;
    __syncthreads();
    float M = fmaxf(fmaxf(fmaxf(shm[0], shm[1]), fmaxf(shm[2], shm[3])),
                    fmaxf(fmaxf(shm[4], shm[5]), fmaxf(shm[6], shm[7])));

    v.x = expf(v.x - M); v.y = expf(v.y - M);
    v.z = expf(v.z - M); v.w = expf(v.w - M);
    float s = v.x + v.y + v.z + v.w;
    __shared__ float shs[8];
    #pragma unroll
    for (int o = 16; o; o >>= 1) s += __shfl_xor_sync(0xFFFFFFFFu, s, o);
    if ((t & 31) == 0) shs[t >> 5] = s;
    __syncthreads();
    float total = shs[0] + shs[1] + shs[2] + shs[3] + shs[4] + shs[5] + shs[6] + shs[7];
    float inv = 1.0f / total;
    v.x *= inv; v.y *= inv; v.z *= inv; v.w *= inv;
    p[t] = v;
}

// ---------------------------------------------------------------------------
// Row LayerNorm over 512 elements. grid = 4096 rows, 128 threads (float4).
// ---------------------------------------------------------------------------
__global__ __launch_bounds__(128) void ln_k(const float* __restrict__ in,
                                            const float* __restrict__ g,
                                            const float* __restrict__ be,
                                            float* __restrict__ out)
{
    const int row = blockIdx.x;
    const int t = threadIdx.x;
    const float4 v = reinterpret_cast<const float4*>(in + (long)row * D_)[t];

    float s  = v.x + v.y + v.z + v.w;
    float sq = v.x * v.x + v.y * v.y + v.z * v.z + v.w * v.w;
    #pragma unroll
    for (int o = 16; o; o >>= 1) {
        s  += __shfl_xor_sync(0xFFFFFFFFu, s, o);
        sq += __shfl_xor_sync(0xFFFFFFFFu, sq, o);
    }
    __shared__ float sh0[4], sh1[4];
    if ((t & 31) == 0) { sh0[t >> 5] = s; sh1[t >> 5] = sq; }
    __syncthreads();
    s  = sh0[0] + sh0[1] + sh0[2] + sh0[3];
    sq = sh1[0] + sh1[1] + sh1[2] + sh1[3];

    const float mean = s * (1.0f / D_);
    const float var  = sq * (1.0f / D_) - mean * mean;
    const float inv  = rsqrtf(var + LN_EPS);

    const float4 gg = reinterpret_cast<const float4*>(g)[t];
    const float4 bb = reinterpret_cast<const float4*>(be)[t];
    float4 o4;
    o4.x = (v.x - mean) * inv * gg.x + bb.x;
    o4.y = (v.y - mean) * inv * gg.y + bb.y;
    o4.z = (v.z - mean) * inv * gg.z + bb.z;
    o4.w = (v.w - mean) * inv * gg.w + bb.w;
    reinterpret_cast<float4*>(out + (long)row * D_)[t] = o4;
}

// ---------------------------------------------------------------------------
// Host driver
// ---------------------------------------------------------------------------
extern "C" void kernel_launch(void* const* d_in, const int* in_sizes, int n_in,
                              void* d_out, int out_size)
{
    const float* x   = (const float*)d_in[0];
    const float* wq  = (const float*)d_in[1];
    const float* bq  = (const float*)d_in[2];
    const float* wk  = (const float*)d_in[3];
    const float* bk  = (const float*)d_in[4];
    const float* wv  = (const float*)d_in[5];
    const float* bv  = (const float*)d_in[6];
    const float* wo  = (const float*)d_in[7];
    const float* bo  = (const float*)d_in[8];
    const float* g1  = (const float*)d_in[9];
    const float* be1 = (const float*)d_in[10];
    const float* w1  = (const float*)d_in[11];
    const float* b1  = (const float*)d_in[12];
    const float* w2  = (const float*)d_in[13];
    const float* b2  = (const float*)d_in[14];
    const float* g2  = (const float*)d_in[15];
    const float* be2 = (const float*)d_in[16];

    float *gx, *gq, *gk, *gv, *gattn, *gtmp, *gffn, *gsc;
    cudaGetSymbolAddress((void**)&gx,    g_x);
    cudaGetSymbolAddress((void**)&gq,    g_q);
    cudaGetSymbolAddress((void**)&gk,    g_kk);
    cudaGetSymbolAddress((void**)&gv,    g_vv);
    cudaGetSymbolAddress((void**)&gattn, g_attn);
    cudaGetSymbolAddress((void**)&gtmp,  g_tmp);
    cudaGetSymbolAddress((void**)&gffn,  g_ffn);
    cudaGetSymbolAddress((void**)&gsc,   g_sc);

    cudaMemcpyAsync(gx, x, (size_t)M_ROWS * D_ * sizeof(float),
                    cudaMemcpyDeviceToDevice, 0);

    const dim3 gProj(D_ / 128, M_ROWS / 128, 1);   // (4, 32)
    const dim3 gScore(S_ / 128, S_ / 128, B_ * H_); // (8, 8, 32)
    const dim3 gPV(1, S_ / 128, B_ * H_);           // (1, 8, 32)
    const dim3 gFFN1(F_ / 128, M_ROWS / 128, 1);    // (16, 32)

    for (int l = 0; l < L_; l++) {
        const float* wq_l = wq + (long)l * D_ * D_;
        const float* wk_l = wk + (long)l * D_ * D_;
        const float* wv_l = wv + (long)l * D_ * D_;
        const float* wo_l = wo + (long)l * D_ * D_;
        const float* w1_l = w1 + (long)l * D_ * F_;
        const float* w2_l = w2 + (long)l * F_ * D_;
        const float* bq_l = bq + (long)l * D_;
        const float* bk_l = bk + (long)l * D_;
        const float* bv_l = bv + (long)l * D_;
        const float* bo_l = bo + (long)l * D_;
        const float* b1_l = b1 + (long)l * F_;
        const float* b2_l = b2 + (long)l * D_;
        const float* g1_l = g1 + (long)l * D_;
        const float* g2_l = g2 + (long)l * D_;
        const float* be1_l = be1 + (long)l * D_;
        const float* be2_l = be2 + (long)l * D_;

        // Q, K, V projections -> [B,H,S,DH] (Q pre-scaled by 1/sqrt(DH))
        gemm_k<128,128,8,8,8,false,M_HEADS><<<gProj, 256>>>(
            gx, wq_l, bq_l, nullptr, gq, M_ROWS, D_, D_, D_, D_, 0, 0, 0, QK_SCALE);
        gemm_k<128,128,8,8,8,false,M_HEADS><<<gProj, 256>>>(
            gx, wk_l, bk_l, nullptr, gk, M_ROWS, D_, D_, D_, D_, 0, 0, 0, 1.0f);
        gemm_k<128,128,8,8,8,false,M_HEADS><<<gProj, 256>>>(
            gx, wv_l, bv_l, nullptr, gv, M_ROWS, D_, D_, D_, D_, 0, 0, 0, 1.0f);

        // Scores = Q K^T (batched over B*H)
        gemm_k<128,128,8,8,8,true,M_SCORES><<<gScore, 256>>>(
            gq, gk, nullptr, nullptr, gsc, S_, S_, DH_, DH_, DH_,
            (long)S_ * DH_, (long)S_ * DH_, (long)S_ * S_, 1.0f);

        // Softmax rows
        softmax_k<<<B_ * H_ * S_, 256>>>(gsc);

        // Attn = P V  (batched), write back to [B,S,D]
        gemm_k<128,64,8,8,4,false,M_PV><<<gPV, 256>>>(
            gsc, gv, nullptr, nullptr, gattn, S_, DH_, S_, S_, DH_,
            (long)S_ * S_, (long)S_ * DH_, 0, 1.0f);

        // O projection + residual
        gemm_k<128,128,8,8,8,false,M_RES><<<gProj, 256>>>(
            gattn, wo_l, bo_l, gx, gtmp, M_ROWS, D_, D_, D_, D_, 0, 0, 0, 1.0f);
        // LayerNorm1 -> gx
        ln_k<<<M_ROWS, 128>>>(gtmp, g1_l, be1_l, gx);

        // FFN1 + exact GELU
        gemm_k<128,128,8,8,8,false,M_GELU><<<gFFN1, 256>>>(
            gx, w1_l, b1_l, nullptr, gffn, M_ROWS, F_, D_, D_, F_, 0, 0, 0, 1.0f);
        // FFN2 + residual
        gemm_k<128,128,8,8,8,false,M_RES><<<gProj, 256>>>(
            gffn, w2_l, b2_l, gx, gtmp, M_ROWS, D_, F_, F_, D_, 0, 0, 0, 1.0f);
        // LayerNorm2 -> gx (or d_out on last layer)
        ln_k<<<M_ROWS, 128>>>(gtmp, g2_l, be2_l,
                              (l == L_ - 1) ? (float*)d_out : gx);
    }
}

// round 2
// speedup vs baseline: 3.1969x; 3.1969x over previous
#include <cuda_runtime.h>
#include <math.h>
#include <stdint.h>

// Problem constants
static constexpr int B_ = 4, S_ = 1024, D_ = 512, H_ = 8, F_ = 2048, DH_ = 64, L_ = 8;
static constexpr int M_ROWS = B_ * S_;           // 4096
static constexpr float QK_SCALE = 0.125f;        // 1/sqrt(64)
static constexpr float LN_EPS = 1e-5f;

// Scratch (device globals; no allocation anywhere)
__device__ float g_x[M_ROWS * D_];
__device__ float g_q[M_ROWS * D_];
__device__ float g_kk[M_ROWS * D_];
__device__ float g_vv[M_ROWS * D_];
__device__ float g_attn[M_ROWS * D_];
__device__ float g_tmp[M_ROWS * D_];
__device__ float g_ffn[M_ROWS * F_];
__device__ float g_sc[(size_t)B_ * H_ * S_ * S_];                  // 134 MB
__device__ float g_wr[(size_t)L_ * (4 * D_ * D_ + 2 * D_ * F_)];   // tf32-rounded weights, 96 MB

static constexpr long LDD = (long)L_ * D_ * D_;
static constexpr long LDF = (long)L_ * D_ * F_;
// offsets into g_wr: wq, wk, wv, wo, w1, w2
static constexpr long OFF_WQ = 0, OFF_WK = LDD, OFF_WV = 2 * LDD, OFF_WO = 3 * LDD;
static constexpr long OFF_W1 = 4 * LDD, OFF_W2 = 4 * LDD + LDF;

enum { M_HEADS = 1, M_RES = 2, M_GELU = 3, M_SCORES = 4, M_PV = 5 };

// ---------------------------------------------------------------------------
// helpers
// ---------------------------------------------------------------------------
__device__ __forceinline__ uint32_t f2tf(float x) {
    uint32_t r;
    asm("cvt.rna.tf32.f32 %0, %1;" : "=r"(r) : "f"(x));
    return r;
}

__device__ __forceinline__ void cpa16(uint32_t smem, const void* gptr) {
    asm volatile("cp.async.cg.shared.global [%0], [%1], 16;\n" :: "r"(smem), "l"(gptr));
}
__device__ __forceinline__ void cp_commit() {
    asm volatile("cp.async.commit_group;\n" ::);
}
template <int N>
__device__ __forceinline__ void cp_wait() {
    asm volatile("cp.async.wait_group %0;\n" :: "n"(N));
}

__device__ __forceinline__ void mma8(float* c, const uint32_t* a, const uint32_t* b) {
    asm("mma.sync.aligned.m16n8k8.row.col.f32.tf32.tf32.f32 "
        "{%0,%1,%2,%3}, {%4,%5,%6,%7}, {%8,%9}, {%0,%1,%2,%3};"
        : "+f"(c[0]), "+f"(c[1]), "+f"(c[2]), "+f"(c[3])
        : "r"(a[0]), "r"(a[1]), "r"(a[2]), "r"(a[3]), "r"(b[0]), "r"(b[1]));
}

// ---------------------------------------------------------------------------
// tf32 tensor-core GEMM, cp.async double-buffered, compile-time epilogues.
// C(z)[m,n] = A(z)[m,k] * B(z)[k,n]   (TRANSB: B stored [n,k])
// B operand must be pre-rounded to tf32; A is cvt.rna'd in-register.
// ---------------------------------------------------------------------------
template <int BM, int BN, int BK, int WM, int WN, bool TRANSB, int MODE>
__global__ __launch_bounds__(256)
void mma_gemm(const float* __restrict__ A, const float* __restrict__ Bm,
              const float* __restrict__ bias, const float* __restrict__ res,
              float* __restrict__ C, int M, int N, int K, int lda, int ldb,
              long sA, long sB, long sC, float alpha)
{
    constexpr int WARPS_M = BM / WM, WARPS_N = BN / WN;
    constexpr int THREADS = WARPS_M * WARPS_N * 32;
    static_assert(THREADS == 256, "expect 8 warps");
    constexpr int MI = WM / 16, NI = WN / 8;
    constexpr int PADA = 4;
    constexpr int PADB = TRANSB ? 4 : 8;
    constexpr int BROWS = TRANSB ? BN : BK;
    constexpr int BCOLS = TRANSB ? BK : BN;

    __shared__ alignas(16) float As[2][BM][BK + PADA];
    __shared__ alignas(16) float Bs[2][BROWS][BCOLS + PADB];

    const int z = blockIdx.z;
    A  += (long)z * sA;
    Bm += (long)z * sB;
    C  += (long)z * sC;

    const int bm = blockIdx.y * BM;
    const int bn = blockIdx.x * BN;
    const int tid = threadIdx.x;
    const int lane = tid & 31;
    const int warp = tid >> 5;
    const int wm0 = (warp / WARPS_N) * WM;
    const int wn0 = (warp % WARPS_N) * WN;
    const int lr = lane >> 2;   // groupID
    const int lc = lane & 3;    // threadID_in_group

    float acc[MI][NI][4];
    #pragma unroll
    for (int i = 0; i < MI; i++)
        #pragma unroll
        for (int j = 0; j < NI; j++)
            #pragma unroll
            for (int q = 0; q < 4; q++) acc[i][j][q] = 0.0f;

    constexpr int CHA = BM * BK / 4;
    constexpr int CHB = BROWS * BCOLS / 4;

    auto load_stage = [&](int st, int k0) {
        #pragma unroll
        for (int c = tid; c < CHA; c += THREADS) {
            int r = c / (BK / 4), cc = (c % (BK / 4)) * 4;
            cpa16((uint32_t)__cvta_generic_to_shared(&As[st][r][cc]),
                  A + (long)(bm + r) * lda + k0 + cc);
        }
        if (TRANSB) {
            #pragma unroll
            for (int c = tid; c < CHB; c += THREADS) {
                int r = c / (BK / 4), cc = (c % (BK / 4)) * 4;
                cpa16((uint32_t)__cvta_generic_to_shared(&Bs[st][r][cc]),
                      Bm + (long)(bn + r) * ldb + k0 + cc);
            }
        } else {
            #pragma unroll
            for (int c = tid; c < CHB; c += THREADS) {
                int r = c / (BN / 4), cc = (c % (BN / 4)) * 4;
                cpa16((uint32_t)__cvta_generic_to_shared(&Bs[st][r][cc]),
                      Bm + (long)(k0 + r) * ldb + bn + cc);
            }
        }
        cp_commit();
    };

    const int NIT = K / BK;
    load_stage(0, 0);

    for (int it = 0; it < NIT; it++) {
        if (it + 1 < NIT) {
            load_stage((it + 1) & 1, (it + 1) * BK);
            cp_wait<1>();
        } else {
            cp_wait<0>();
        }
        __syncthreads();

        const int st = it & 1;
        #pragma unroll
        for (int kk = 0; kk < BK; kk += 8) {
            uint32_t af[MI][4];
            #pragma unroll
            for (int mi = 0; mi < MI; mi++) {
                af[mi][0] = f2tf(As[st][wm0 + mi * 16 + lr    ][kk + lc    ]);
                af[mi][1] = f2tf(As[st][wm0 + mi * 16 + lr + 8][kk + lc    ]);
                af[mi][2] = f2tf(As[st][wm0 + mi * 16 + lr    ][kk + lc + 4]);
                af[mi][3] = f2tf(As[st][wm0 + mi * 16 + lr + 8][kk + lc + 4]);
            }
            uint32_t bf[NI][2];
            #pragma unroll
            for (int ni = 0; ni < NI; ni++) {
                if (TRANSB) {
                    bf[ni][0] = __float_as_uint(Bs[st][wn0 + ni * 8 + lr][kk + lc    ]);
                    bf[ni][1] = __float_as_uint(Bs[st][wn0 + ni * 8 + lr][kk + lc + 4]);
                } else {
                    bf[ni][0] = __float_as_uint(Bs[st][kk + lc    ][wn0 + ni * 8 + lr]);
                    bf[ni][1] = __float_as_uint(Bs[st][kk + lc + 4][wn0 + ni * 8 + lr]);
                }
            }
            #pragma unroll
            for (int mi = 0; mi < MI; mi++)
                #pragma unroll
                for (int ni = 0; ni < NI; ni++)
                    mma8(acc[mi][ni], af[mi], bf[ni]);
        }
        __syncthreads();
    }

    // Epilogue: per fragment, two consecutive columns.
    #pragma unroll
    for (int mi = 0; mi < MI; mi++) {
        #pragma unroll
        for (int ni = 0; ni < NI; ni++) {
            #pragma unroll
            for (int ri = 0; ri < 2; ri++) {
                const int m = bm + wm0 + mi * 16 + lr + ri * 8;
                const int n = bn + wn0 + ni * 8 + lc * 2;
                float v0 = acc[mi][ni][ri * 2 + 0];
                float v1 = acc[mi][ni][ri * 2 + 1];
                if (MODE == M_HEADS) {
                    v0 = (v0 + bias[n]) * alpha;
                    v1 = (v1 + bias[n + 1]) * alpha;
                    v0 = __uint_as_float(f2tf(v0));   // pre-round for tf32 B-operand use
                    v1 = __uint_as_float(f2tf(v1));
                    int b = m >> 10, s = m & 1023, h = n >> 6, dh = n & 63;
                    long base = (((long)(b * H_ + h) * S_ + s) << 6) + dh;
                    C[base] = v0; C[base + 1] = v1;
                } else if (MODE == M_RES) {
                    long o = (long)m * N + n;
                    C[o]     = v0 + bias[n]     + res[o];
                    C[o + 1] = v1 + bias[n + 1] + res[o + 1];
                } else if (MODE == M_GELU) {
                    v0 += bias[n]; v1 += bias[n + 1];
                    long o = (long)m * N + n;
                    C[o]     = 0.5f * v0 * (1.0f + erff(v0 * 0.70710678118654752f));
                    C[o + 1] = 0.5f * v1 * (1.0f + erff(v1 * 0.70710678118654752f));
                } else if (MODE == M_SCORES) {
                    long o = (long)m * N + n;
                    C[o] = v0; C[o + 1] = v1;
                } else { // M_PV
                    int b = z >> 3, h = z & 7;
                    long o = ((long)(b * S_ + m)) * D_ + h * DH_ + n;
                    C[o] = v0; C[o + 1] = v1;
                }
            }
        }
    }
}

// ---------------------------------------------------------------------------
// Round weights to tf32 (RNA) once per launch. n divisible by 4.
// ---------------------------------------------------------------------------
__global__ __launch_bounds__(256) void roundw_k(const float* __restrict__ in,
                                               float* __restrict__ out, int n4)
{
    int i = blockIdx.x * blockDim.x + threadIdx.x;
    int stride = gridDim.x * blockDim.x;
    const float4* in4 = reinterpret_cast<const float4*>(in);
    float4* out4 = reinterpret_cast<float4*>(out);
    for (; i < n4; i += stride) {
        float4 v = in4[i];
        v.x = __uint_as_float(f2tf(v.x));
        v.y = __uint_as_float(f2tf(v.y));
        v.z = __uint_as_float(f2tf(v.z));
        v.w = __uint_as_float(f2tf(v.w));
        out4[i] = v;
    }
}

// ---------------------------------------------------------------------------
// Row softmax over 1024 elements, in place. grid = B*H*S rows, 256 threads.
// ---------------------------------------------------------------------------
__global__ __launch_bounds__(256) void softmax_k(float* __restrict__ Sc)
{
    const size_t row = blockIdx.x;
    float4* p = reinterpret_cast<float4*>(Sc + row * (size_t)S_);
    const int t = threadIdx.x;
    float4 v = p[t];

    float m = fmaxf(fmaxf(v.x, v.y), fmaxf(v.z, v.w));
    __shared__ float shm[8];
    #pragma unroll
    for (int o = 16; o; o >>= 1) m = fmaxf(m, __shfl_xor_sync(0xFFFFFFFFu, m, o));
    if ((t & 31) == 0) shm[t >> 5] = m;
    __syncthreads();
    float M = fmaxf(fmaxf(fmaxf(shm[0], shm[1]), fmaxf(shm[2], shm[3])),
                    fmaxf(fmaxf(shm[4], shm[5]), fmaxf(shm[6], shm[7])));

    v.x = expf(v.x - M); v.y = expf(v.y - M);
    v.z = expf(v.z - M); v.w = expf(v.w - M);
    float s = v.x + v.y + v.z + v.w;
    __shared__ float shs[8];
    #pragma unroll
    for (int o = 16; o; o >>= 1) s += __shfl_xor_sync(0xFFFFFFFFu, s, o);
    if ((t & 31) == 0) shs[t >> 5] = s;
    __syncthreads();
    float total = shs[0] + shs[1] + shs[2] + shs[3] + shs[4] + shs[5] + shs[6] + shs[7];
    float inv = 1.0f / total;
    v.x *= inv; v.y *= inv; v.z *= inv; v.w *= inv;
    p[t] = v;
}

// ---------------------------------------------------------------------------
// Row LayerNorm over 512 elements. grid = 4096 rows, 128 threads (float4).
// ---------------------------------------------------------------------------
__global__ __launch_bounds__(128) void ln_k(const float* __restrict__ in,
                                            const float* __restrict__ g,
                                            const float* __restrict__ be,
                                            float* __restrict__ out)
{
    const int row = blockIdx.x;
    const int t = threadIdx.x;
    const float4 v = reinterpret_cast<const float4*>(in + (long)row * D_)[t];

    float s  = v.x + v.y + v.z + v.w;
    float sq = v.x * v.x + v.y * v.y + v.z * v.z + v.w * v.w;
    #pragma unroll
    for (int o = 16; o; o >>= 1) {
        s  += __shfl_xor_sync(0xFFFFFFFFu, s, o);
        sq += __shfl_xor_sync(0xFFFFFFFFu, sq, o);
    }
    __shared__ float sh0[4], sh1[4];
    if ((t & 31) == 0) { sh0[t >> 5] = s; sh1[t >> 5] = sq; }
    __syncthreads();
    s  = sh0[0] + sh0[1] + sh0[2] + sh0[3];
    sq = sh1[0] + sh1[1] + sh1[2] + sh1[3];

    const float mean = s * (1.0f / D_);
    const float var  = sq * (1.0f / D_) - mean * mean;
    const float inv  = rsqrtf(var + LN_EPS);

    const float4 gg = reinterpret_cast<const float4*>(g)[t];
    const float4 bb = reinterpret_cast<const float4*>(be)[t];
    float4 o4;
    o4.x = (v.x - mean) * inv * gg.x + bb.x;
    o4.y = (v.y - mean) * inv * gg.y + bb.y;
    o4.z = (v.z - mean) * inv * gg.z + bb.z;
    o4.w = (v.w - mean) * inv * gg.w + bb.w;
    reinterpret_cast<float4*>(out + (long)row * D_)[t] = o4;
}

// ---------------------------------------------------------------------------
// Host driver
// ---------------------------------------------------------------------------
extern "C" void kernel_launch(void* const* d_in, const int* in_sizes, int n_in,
                              void* d_out, int out_size)
{
    const float* x   = (const float*)d_in[0];
    const float* wq  = (const float*)d_in[1];
    const float* bq  = (const float*)d_in[2];
    const float* wk  = (const float*)d_in[3];
    const float* bk  = (const float*)d_in[4];
    const float* wv  = (const float*)d_in[5];
    const float* bv  = (const float*)d_in[6];
    const float* wo  = (const float*)d_in[7];
    const float* bo  = (const float*)d_in[8];
    const float* g1  = (const float*)d_in[9];
    const float* be1 = (const float*)d_in[10];
    const float* w1  = (const float*)d_in[11];
    const float* b1  = (const float*)d_in[12];
    const float* w2  = (const float*)d_in[13];
    const float* b2  = (const float*)d_in[14];
    const float* g2  = (const float*)d_in[15];
    const float* be2 = (const float*)d_in[16];

    float *gx, *gq, *gk, *gv, *gattn, *gtmp, *gffn, *gsc, *gwr;
    cudaGetSymbolAddress((void**)&gx,    g_x);
    cudaGetSymbolAddress((void**)&gq,    g_q);
    cudaGetSymbolAddress((void**)&gk,    g_kk);
    cudaGetSymbolAddress((void**)&gv,    g_vv);
    cudaGetSymbolAddress((void**)&gattn, g_attn);
    cudaGetSymbolAddress((void**)&gtmp,  g_tmp);
    cudaGetSymbolAddress((void**)&gffn,  g_ffn);
    cudaGetSymbolAddress((void**)&gsc,   g_sc);
    cudaGetSymbolAddress((void**)&gwr,   g_wr);

    cudaMemcpyAsync(gx, x, (size_t)M_ROWS * D_ * sizeof(float),
                    cudaMemcpyDeviceToDevice, 0);

    // Pre-round all weights to tf32 (RNA) into scratch.
    roundw_k<<<1024, 256>>>(wq, gwr + OFF_WQ, (int)(LDD / 4));
    roundw_k<<<1024, 256>>>(wk, gwr + OFF_WK, (int)(LDD / 4));
    roundw_k<<<1024, 256>>>(wv, gwr + OFF_WV, (int)(LDD / 4));
    roundw_k<<<1024, 256>>>(wo, gwr + OFF_WO, (int)(LDD / 4));
    roundw_k<<<1024, 256>>>(w1, gwr + OFF_W1, (int)(LDF / 4));
    roundw_k<<<1024, 256>>>(w2, gwr + OFF_W2, (int)(LDF / 4));

    const dim3 gProj(D_ / 128, M_ROWS / 128, 1);    // (4, 32)
    const dim3 gScore(S_ / 128, S_ / 128, B_ * H_); // (8, 8, 32)
    const dim3 gPV(1, S_ / 128, B_ * H_);           // (1, 8, 32)
    const dim3 gFFN1(F_ / 128, M_ROWS / 128, 1);    // (16, 32)

    for (int l = 0; l < L_; l++) {
        const float* wq_l = gwr + OFF_WQ + (long)l * D_ * D_;
        const float* wk_l = gwr + OFF_WK + (long)l * D_ * D_;
        const float* wv_l = gwr + OFF_WV + (long)l * D_ * D_;
        const float* wo_l = gwr + OFF_WO + (long)l * D_ * D_;
        const float* w1_l = gwr + OFF_W1 + (long)l * D_ * F_;
        const float* w2_l = gwr + OFF_W2 + (long)l * F_ * D_;
        const float* bq_l = bq + (long)l * D_;
        const float* bk_l = bk + (long)l * D_;
        const float* bv_l = bv + (long)l * D_;
        const float* bo_l = bo + (long)l * D_;
        const float* b1_l = b1 + (long)l * F_;
        const float* b2_l = b2 + (long)l * D_;
        const float* g1_l = g1 + (long)l * D_;
        const float* g2_l = g2 + (long)l * D_;
        const float* be1_l = be1 + (long)l * D_;
        const float* be2_l = be2 + (long)l * D_;

        // Q, K, V projections -> [B,H,S,DH] (Q pre-scaled, all tf32-rounded)
        mma_gemm<128,128,16,32,64,false,M_HEADS><<<gProj, 256>>>(
            gx, wq_l, bq_l, nullptr, gq, M_ROWS, D_, D_, D_, D_, 0, 0, 0, QK_SCALE);
        mma_gemm<128,128,16,32,64,false,M_HEADS><<<gProj, 256>>>(
            gx, wk_l, bk_l, nullptr, gk, M_ROWS, D_, D_, D_, D_, 0, 0, 0, 1.0f);
        mma_gemm<128,128,16,32,64,false,M_HEADS><<<gProj, 256>>>(
            gx, wv_l, bv_l, nullptr, gv, M_ROWS, D_, D_, D_, D_, 0, 0, 0, 1.0f);

        // Scores = Q K^T (batched over B*H)
        mma_gemm<128,128,16,32,64,true,M_SCORES><<<gScore, 256>>>(
            gq, gk, nullptr, nullptr, gsc, S_, S_, DH_, DH_, DH_,
            (long)S_ * DH_, (long)S_ * DH_, (long)S_ * S_, 1.0f);

        // Softmax rows
        softmax_k<<<B_ * H_ * S_, 256>>>(gsc);

        // Attn = P V (batched), write back to [B,S,D]
        mma_gemm<128,64,16,32,32,false,M_PV><<<gPV, 256>>>(
            gsc, gv, nullptr, nullptr, gattn, S_, DH_, S_, S_, DH_,
            (long)S_ * S_, (long)S_ * DH_, 0, 1.0f);

        // O projection + residual
        mma_gemm<128,128,16,32,64,false,M_RES><<<gProj, 256>>>(
            gattn, wo_l, bo_l, gx, gtmp, M_ROWS, D_, D_, D_, D_, 0, 0, 0, 1.0f);
        ln_k<<<M_ROWS, 128>>>(gtmp, g1_l, be1_l, gx);

        // FFN1 + exact GELU
        mma_gemm<128,128,16,32,64,false,M_GELU><<<gFFN1, 256>>>(
            gx, w1_l, b1_l, nullptr, gffn, M_ROWS, F_, D_, D_, F_, 0, 0, 0, 1.0f);
        // FFN2 + residual
        mma_gemm<128,128,16,32,64,false,M_RES><<<gProj, 256>>>(
            gffn, w2_l, b2_l, gx, gtmp, M_ROWS, D_, F_, F_, D_, 0, 0, 0, 1.0f);
        ln_k<<<M_ROWS, 128>>>(gtmp, g2_l, be2_l,
                              (l == L_ - 1) ? (float*)d_out : gx);
    }
}

// round 4
// speedup vs baseline: 3.4621x; 1.0829x over previous
#include <cuda_runtime.h>
#include <math.h>
#include <stdint.h>

// Problem constants
static constexpr int B_ = 4, S_ = 1024, D_ = 512, H_ = 8, F_ = 2048, DH_ = 64, L_ = 8;
static constexpr int M_ROWS = B_ * S_;           // 4096
static constexpr float QK_SCALE = 0.125f;        // 1/sqrt(64)
static constexpr float LN_EPS = 1e-5f;

static constexpr long MD = (long)M_ROWS * D_;
// transposed+rounded weight slabs: [N,K] row-major per layer
static constexpr long SZ_QKV = 1536L * 512, SZ_O = 512L * 512, SZ_1 = 2048L * 512, SZ_2 = 512L * 2048;
static constexpr long OFF_TQKV = 0, OFF_TO = 8 * SZ_QKV, OFF_T1 = OFF_TO + 8 * SZ_O, OFF_T2 = OFF_T1 + 8 * SZ_1;

// Scratch (device globals; no allocation anywhere)
__device__ float g_x[M_ROWS * D_];        // exact fp32 residual stream
__device__ float g_xr[M_ROWS * D_];       // tf32-rounded copy for GEMM A
__device__ float g_qkv[3 * M_ROWS * D_];  // q/k/v slabs [B,H,S,DH], rounded
__device__ float g_attn[M_ROWS * D_];     // rounded
__device__ float g_tmp[M_ROWS * D_];
__device__ float g_ffn[M_ROWS * F_];      // rounded
__device__ float g_sc[(size_t)B_ * H_ * S_ * S_];          // 134 MB
__device__ float g_wT[8 * (SZ_QKV + SZ_O + SZ_1 + SZ_2)];  // ~101 MB

enum { M_RES = 2, M_GELU = 3, M_SCORES = 4, M_PV = 5, M_QKV = 6 };

// ---------------------------------------------------------------------------
// helpers
// ---------------------------------------------------------------------------
__device__ __forceinline__ uint32_t f2tf(float x) {
    uint32_t r;
    asm("cvt.rna.tf32.f32 %0, %1;" : "=r"(r) : "f"(x));
    return r;
}
__device__ __forceinline__ float frnd(float x) { return __uint_as_float(f2tf(x)); }

__device__ __forceinline__ void cpa16(uint32_t smem, const void* gptr) {
    asm volatile("cp.async.cg.shared.global [%0], [%1], 16;\n" :: "r"(smem), "l"(gptr));
}
__device__ __forceinline__ void cp_commit() {
    asm volatile("cp.async.commit_group;\n" ::);
}
template <int N>
__device__ __forceinline__ void cp_wait() {
    asm volatile("cp.async.wait_group %0;\n" :: "n"(N));
}
__device__ __forceinline__ uint32_t smem_u32(const void* p) {
    return (uint32_t)__cvta_generic_to_shared(p);
}

__device__ __forceinline__ void mma8(float* c, const uint32_t* a, const uint32_t* b) {
    asm("mma.sync.aligned.m16n8k8.row.col.f32.tf32.tf32.f32 "
        "{%0,%1,%2,%3}, {%4,%5,%6,%7}, {%8,%9}, {%0,%1,%2,%3};"
        : "+f"(c[0]), "+f"(c[1]), "+f"(c[2]), "+f"(c[3])
        : "r"(a[0]), "r"(a[1]), "r"(a[2]), "r"(a[3]), "r"(b[0]), "r"(b[1]));
}

// ---------------------------------------------------------------------------
// tf32 mma.sync GEMM: 128 threads, 4 warps of 64xWN, BK=32, 3-stage cp.async.
// C(z)[m,n] = A(z)[m,k] * B(z)[k,n]  (TRANSB: B stored [n,k]).
// All operands must be pre-rounded to tf32 (no cvt in mainloop).
// ---------------------------------------------------------------------------
template <int BM, int BN, bool TRANSB>
static constexpr int smem_bytes() {
    // A: BM rows x (32+4); B: TRANSB ? BN x (32+4) : 32 x (BN+8); 3 stages
    return 3 * (BM * 36 + (TRANSB ? BN * 36 : 32 * (BN + 8))) * 4;
}

template <int BM, int BN, bool TRANSB, int MODE>
__global__ __launch_bounds__(128)
void mma_gemm(const float* __restrict__ A, const float* __restrict__ Bm,
              const float* __restrict__ b0, const float* __restrict__ b1,
              const float* __restrict__ b2, const float* __restrict__ res,
              float* __restrict__ C, int N, int K, int lda, int ldb,
              long sA, long sB, long sC)
{
    constexpr int BK = 32;
    constexpr int WM = 64, WN = BN / 2;
    constexpr int MI = WM / 16, NI = WN / 8;           // 4, (8|4)
    constexpr int ASTR = BK + 4;                       // 36 floats
    constexpr int ASZ = BM * ASTR;                     // floats per A stage
    constexpr int BSTR = TRANSB ? ASTR : (BN + 8);
    constexpr int BROWS = TRANSB ? BN : BK;
    constexpr int BSZ = BROWS * BSTR;

    extern __shared__ float sm[];
    float* As = sm;                 // [3][ASZ]
    float* Bs = sm + 3 * ASZ;       // [3][BSZ]

    const int z = blockIdx.z;
    A  += (long)z * sA;
    Bm += (long)z * sB;
    C  += (long)z * sC;

    const int bm = blockIdx.y * BM;
    const int bn = blockIdx.x * BN;
    const int tid = threadIdx.x;
    const int lane = tid & 31;
    const int warp = tid >> 5;
    const int wm0 = (warp >> 1) * WM;      // 2x2 warp grid
    const int wn0 = (warp & 1) * WN;
    const int lr = lane >> 2;
    const int lc = lane & 3;

    float acc[MI][NI][4];
    #pragma unroll
    for (int i = 0; i < MI; i++)
        #pragma unroll
        for (int j = 0; j < NI; j++)
            #pragma unroll
            for (int q = 0; q < 4; q++) acc[i][j][q] = 0.0f;

    auto load_stage = [&](int j) {
        const int st = j % 3;
        float* as = As + st * ASZ;
        // A tile: BM x 32, vector along k
        #pragma unroll
        for (int c = tid; c < BM * 8; c += 128) {
            int r = c >> 3, q = c & 7;
            cpa16(smem_u32(as + r * ASTR + q * 4),
                  A + (long)(bm + r) * lda + j * BK + q * 4);
        }
        float* bs = Bs + st * BSZ;
        if (TRANSB) {
            #pragma unroll
            for (int c = tid; c < BN * 8; c += 128) {
                int r = c >> 3, q = c & 7;
                cpa16(smem_u32(bs + r * BSTR + q * 4),
                      Bm + (long)(bn + r) * ldb + j * BK + q * 4);
            }
        } else {
            constexpr int QB = BN / 4;
            #pragma unroll
            for (int c = tid; c < 32 * QB; c += 128) {
                int r = c / QB, q = c % QB;
                cpa16(smem_u32(bs + r * BSTR + q * 4),
                      Bm + (long)(j * BK + r) * ldb + bn + q * 4);
            }
        }
        cp_commit();
    };

    const int NIT = K / BK;
    load_stage(0);
    if (NIT > 1) load_stage(1);

    for (int it = 0; it < NIT; it++) {
        if (it + 2 < NIT) { load_stage(it + 2); cp_wait<2>(); }
        else if (it + 2 == NIT) { cp_wait<1>(); }
        else { cp_wait<0>(); }
        __syncthreads();

        const int st = it % 3;
        const float* as = As + st * ASZ;
        const float* bs = Bs + st * BSZ;
        #pragma unroll
        for (int kk = 0; kk < BK; kk += 8) {
            uint32_t af[MI][4];
            #pragma unroll
            for (int mi = 0; mi < MI; mi++) {
                const float* ap = as + (wm0 + mi * 16 + lr) * ASTR + kk + lc;
                af[mi][0] = __float_as_uint(ap[0]);
                af[mi][1] = __float_as_uint(ap[8 * ASTR]);
                af[mi][2] = __float_as_uint(ap[4]);
                af[mi][3] = __float_as_uint(ap[8 * ASTR + 4]);
            }
            uint32_t bf[NI][2];
            #pragma unroll
            for (int ni = 0; ni < NI; ni++) {
                if (TRANSB) {
                    const float* bp = bs + (wn0 + ni * 8 + lr) * BSTR + kk + lc;
                    bf[ni][0] = __float_as_uint(bp[0]);
                    bf[ni][1] = __float_as_uint(bp[4]);
                } else {
                    const float* bp = bs + (kk + lc) * BSTR + wn0 + ni * 8 + lr;
                    bf[ni][0] = __float_as_uint(bp[0]);
                    bf[ni][1] = __float_as_uint(bp[4 * BSTR]);
                }
            }
            #pragma unroll
            for (int mi = 0; mi < MI; mi++)
                #pragma unroll
                for (int ni = 0; ni < NI; ni++)
                    mma8(acc[mi][ni], af[mi], bf[ni]);
        }
        __syncthreads();
    }

    // Epilogue
    #pragma unroll
    for (int mi = 0; mi < MI; mi++) {
        #pragma unroll
        for (int ni = 0; ni < NI; ni++) {
            #pragma unroll
            for (int ri = 0; ri < 2; ri++) {
                const int m = bm + wm0 + mi * 16 + lr + ri * 8;
                const int n = bn + wn0 + ni * 8 + lc * 2;
                float v0 = acc[mi][ni][ri * 2 + 0];
                float v1 = acc[mi][ni][ri * 2 + 1];
                if (MODE == M_SCORES) {
                    long o = (long)m * N + n;
                    C[o] = v0; C[o + 1] = v1;
                } else if (MODE == M_PV) {
                    int b = z >> 3, h = z & 7;
                    long o = ((long)(b * S_ + m)) * D_ + h * DH_ + n;
                    C[o]     = frnd(v0);
                    C[o + 1] = frnd(v1);
                } else if (MODE == M_RES) {
                    long o = (long)m * N + n;
                    C[o]     = v0 + b0[n]     + res[o];
                    C[o + 1] = v1 + b0[n + 1] + res[o + 1];
                } else if (MODE == M_GELU) {
                    v0 += b0[n]; v1 += b0[n + 1];
                    long o = (long)m * N + n;
                    C[o]     = frnd(0.5f * v0 * (1.0f + erff(v0 * 0.70710678118654752f)));
                    C[o + 1] = frnd(0.5f * v1 * (1.0f + erff(v1 * 0.70710678118654752f)));
                } else { // M_QKV: n in [0,1536) across q/k/v slabs
                    const int t = n >> 9;
                    const int colD = n & 511;
                    const float* bb = (t == 0) ? b0 : ((t == 1) ? b1 : b2);
                    const float sc = (t == 0) ? QK_SCALE : 1.0f;
                    const int b = m >> 10, s = m & 1023, h = colD >> 6, dh0 = colD & 63;
                    long o = (long)t * MD + (((long)((b << 3) + h) * S_ + s) << 6) + dh0;
                    C[o]     = frnd((v0 + bb[colD]) * sc);
                    C[o + 1] = frnd((v1 + bb[colD + 1]) * sc);
                }
            }
        }
    }
}

// ---------------------------------------------------------------------------
// transpose + tf32-round weights: out[n*K+k] = rna(in[k*N+n]), per layer z
// ---------------------------------------------------------------------------
__global__ __launch_bounds__(256) void transpose_round(
    const float* __restrict__ in, float* __restrict__ out,
    int K, int N, long in_ls, long out_ls)
{
    __shared__ float t[32][33];
    in  += (long)blockIdx.z * in_ls;
    out += (long)blockIdx.z * out_ls;
    const int k0 = blockIdx.y * 32, n0 = blockIdx.x * 32;
    #pragma unroll
    for (int i = threadIdx.y; i < 32; i += 8)
        t[i][threadIdx.x] = in[(long)(k0 + i) * N + n0 + threadIdx.x];
    __syncthreads();
    #pragma unroll
    for (int i = threadIdx.y; i < 32; i += 8)
        out[(long)(n0 + i) * K + k0 + threadIdx.x] = frnd(t[threadIdx.x][i]);
}

// copy x -> gx (exact) and gxr (rounded)
__global__ __launch_bounds__(256) void copyround_k(const float* __restrict__ x,
                                                   float* __restrict__ gx,
                                                   float* __restrict__ gxr, int n4)
{
    int i = blockIdx.x * blockDim.x + threadIdx.x;
    int stride = gridDim.x * blockDim.x;
    const float4* in4 = reinterpret_cast<const float4*>(x);
    for (; i < n4; i += stride) {
        float4 v = in4[i];
        reinterpret_cast<float4*>(gx)[i] = v;
        v.x = frnd(v.x); v.y = frnd(v.y); v.z = frnd(v.z); v.w = frnd(v.w);
        reinterpret_cast<float4*>(gxr)[i] = v;
    }
}

// ---------------------------------------------------------------------------
// Row softmax over 1024 elements, in place; stores tf32-rounded probs.
// ---------------------------------------------------------------------------
__global__ __launch_bounds__(256) void softmax_k(float* __restrict__ Sc)
{
    const size_t row = blockIdx.x;
    float4* p = reinterpret_cast<float4*>(Sc + row * (size_t)S_);
    const int t = threadIdx.x;
    float4 v = p[t];

    float m = fmaxf(fmaxf(v.x, v.y), fmaxf(v.z, v.w));
    __shared__ float shm[8];
    #pragma unroll
    for (int o = 16; o; o >>= 1) m = fmaxf(m, __shfl_xor_sync(0xFFFFFFFFu, m, o));
    if ((t & 31) == 0) shm[t >> 5] = m;
    __syncthreads();
    float M = fmaxf(fmaxf(fmaxf(shm[0], shm[1]), fmaxf(shm[2], shm[3])),
                    fmaxf(fmaxf(shm[4], shm[5]), fmaxf(shm[6], shm[7])));

    v.x = expf(v.x - M); v.y = expf(v.y - M);
    v.z = expf(v.z - M); v.w = expf(v.w - M);
    float s = v.x + v.y + v.z + v.w;
    __shared__ float shs[8];
    #pragma unroll
    for (int o = 16; o; o >>= 1) s += __shfl_xor_sync(0xFFFFFFFFu, s, o);
    if ((t & 31) == 0) shs[t >> 5] = s;
    __syncthreads();
    float total = shs[0] + shs[1] + shs[2] + shs[3] + shs[4] + shs[5] + shs[6] + shs[7];
    float inv = 1.0f / total;
    v.x = frnd(v.x * inv); v.y = frnd(v.y * inv);
    v.z = frnd(v.z * inv); v.w = frnd(v.w * inv);
    p[t] = v;
}

// ---------------------------------------------------------------------------
// Row LayerNorm over 512 elements; exact out + rounded out_r.
// ---------------------------------------------------------------------------
__global__ __launch_bounds__(128) void ln_k(const float* __restrict__ in,
                                            const float* __restrict__ g,
                                            const float* __restrict__ be,
                                            float* __restrict__ out,
                                            float* __restrict__ out_r)
{
    const int row = blockIdx.x;
    const int t = threadIdx.x;
    const float4 v = reinterpret_cast<const float4*>(in + (long)row * D_)[t];

    float s  = v.x + v.y + v.z + v.w;
    float sq = v.x * v.x + v.y * v.y + v.z * v.z + v.w * v.w;
    #pragma unroll
    for (int o = 16; o; o >>= 1) {
        s  += __shfl_xor_sync(0xFFFFFFFFu, s, o);
        sq += __shfl_xor_sync(0xFFFFFFFFu, sq, o);
    }
    __shared__ float sh0[4], sh1[4];
    if ((t & 31) == 0) { sh0[t >> 5] = s; sh1[t >> 5] = sq; }
    __syncthreads();
    s  = sh0[0] + sh0[1] + sh0[2] + sh0[3];
    sq = sh1[0] + sh1[1] + sh1[2] + sh1[3];

    const float mean = s * (1.0f / D_);
    const float var  = sq * (1.0f / D_) - mean * mean;
    const float inv  = rsqrtf(var + LN_EPS);

    const float4 gg = reinterpret_cast<const float4*>(g)[t];
    const float4 bb = reinterpret_cast<const float4*>(be)[t];
    float4 o4;
    o4.x = (v.x - mean) * inv * gg.x + bb.x;
    o4.y = (v.y - mean) * inv * gg.y + bb.y;
    o4.z = (v.z - mean) * inv * gg.z + bb.z;
    o4.w = (v.w - mean) * inv * gg.w + bb.w;
    reinterpret_cast<float4*>(out + (long)row * D_)[t] = o4;
    if (out_r) {
        float4 r4;
        r4.x = frnd(o4.x); r4.y = frnd(o4.y); r4.z = frnd(o4.z); r4.w = frnd(o4.w);
        reinterpret_cast<float4*>(out_r + (long)row * D_)[t] = r4;
    }
}

// ---------------------------------------------------------------------------
// Host driver
// ---------------------------------------------------------------------------
extern "C" void kernel_launch(void* const* d_in, const int* in_sizes, int n_in,
                              void* d_out, int out_size)
{
    const float* x   = (const float*)d_in[0];
    const float* wq  = (const float*)d_in[1];
    const float* bq  = (const float*)d_in[2];
    const float* wk  = (const float*)d_in[3];
    const float* bk  = (const float*)d_in[4];
    const float* wv  = (const float*)d_in[5];
    const float* bv  = (const float*)d_in[6];
    const float* wo  = (const float*)d_in[7];
    const float* bo  = (const float*)d_in[8];
    const float* g1  = (const float*)d_in[9];
    const float* be1 = (const float*)d_in[10];
    const float* w1  = (const float*)d_in[11];
    const float* b1  = (const float*)d_in[12];
    const float* w2  = (const float*)d_in[13];
    const float* b2  = (const float*)d_in[14];
    const float* g2  = (const float*)d_in[15];
    const float* be2 = (const float*)d_in[16];

    float *gx, *gxr, *gqkv, *gattn, *gtmp, *gffn, *gsc, *gwT;
    cudaGetSymbolAddress((void**)&gx,    g_x);
    cudaGetSymbolAddress((void**)&gxr,   g_xr);
    cudaGetSymbolAddress((void**)&gqkv,  g_qkv);
    cudaGetSymbolAddress((void**)&gattn, g_attn);
    cudaGetSymbolAddress((void**)&gtmp,  g_tmp);
    cudaGetSymbolAddress((void**)&gffn,  g_ffn);
    cudaGetSymbolAddress((void**)&gsc,   g_sc);
    cudaGetSymbolAddress((void**)&gwT,   g_wT);

    constexpr int SM_T = smem_bytes<128, 128, true>();   // 110592
    constexpr int SM_PV = smem_bytes<128, 64, false>();  // 82944
    cudaFuncSetAttribute(mma_gemm<128,128,true,M_QKV>,    cudaFuncAttributeMaxDynamicSharedMemorySize, SM_T);
    cudaFuncSetAttribute(mma_gemm<128,128,true,M_SCORES>, cudaFuncAttributeMaxDynamicSharedMemorySize, SM_T);
    cudaFuncSetAttribute(mma_gemm<128,128,true,M_RES>,    cudaFuncAttributeMaxDynamicSharedMemorySize, SM_T);
    cudaFuncSetAttribute(mma_gemm<128,128,true,M_GELU>,   cudaFuncAttributeMaxDynamicSharedMemorySize, SM_T);
    cudaFuncSetAttribute(mma_gemm<128,64,false,M_PV>,     cudaFuncAttributeMaxDynamicSharedMemorySize, SM_PV);

    copyround_k<<<512, 256>>>(x, gx, gxr, M_ROWS * D_ / 4);

    // transpose + round weights into [N,K] slabs
    const dim3 tb(32, 8);
    transpose_round<<<dim3(16, 16, 8), tb>>>(wq, gwT + OFF_TQKV,            512, 512,  (long)D_*D_, SZ_QKV);
    transpose_round<<<dim3(16, 16, 8), tb>>>(wk, gwT + OFF_TQKV + 512*512,  512, 512,  (long)D_*D_, SZ_QKV);
    transpose_round<<<dim3(16, 16, 8), tb>>>(wv, gwT + OFF_TQKV + 1024*512, 512, 512,  (long)D_*D_, SZ_QKV);
    transpose_round<<<dim3(16, 16, 8), tb>>>(wo, gwT + OFF_TO,              512, 512,  (long)D_*D_, SZ_O);
    transpose_round<<<dim3(64, 16, 8), tb>>>(w1, gwT + OFF_T1,              512, 2048, (long)D_*F_, SZ_1);
    transpose_round<<<dim3(16, 64, 8), tb>>>(w2, gwT + OFF_T2,              2048, 512, (long)F_*D_, SZ_2);

    float* gq = gqkv;
    float* gk = gqkv + MD;
    float* gv = gqkv + 2 * MD;

    const dim3 gQKV(1536 / 128, M_ROWS / 128);      // (12, 32)
    const dim3 gOP(512 / 128, M_ROWS / 128);        // (4, 32)
    const dim3 gF1(2048 / 128, M_ROWS / 128);       // (16, 32)
    const dim3 gScore(S_ / 128, S_ / 128, B_ * H_); // (8, 8, 32)
    const dim3 gPV(1, S_ / 128, B_ * H_);           // (1, 8, 32)

    for (int l = 0; l < L_; l++) {
        const float* wqkvT_l = gwT + OFF_TQKV + (long)l * SZ_QKV;
        const float* woT_l   = gwT + OFF_TO   + (long)l * SZ_O;
        const float* w1T_l   = gwT + OFF_T1   + (long)l * SZ_1;
        const float* w2T_l   = gwT + OFF_T2   + (long)l * SZ_2;
        const float* bq_l = bq + (long)l * D_;
        const float* bk_l = bk + (long)l * D_;
        const float* bv_l = bv + (long)l * D_;
        const float* bo_l = bo + (long)l * D_;
        const float* b1_l = b1 + (long)l * F_;
        const float* b2_l = b2 + (long)l * D_;
        const float* g1_l = g1 + (long)l * D_;
        const float* g2_l = g2 + (long)l * D_;
        const float* be1_l = be1 + (long)l * D_;
        const float* be2_l = be2 + (long)l * D_;

        // fused QKV projection -> q/k/v slabs [B,H,S,DH], rounded, Q pre-scaled
        mma_gemm<128,128,true,M_QKV><<<gQKV, 128, SM_T>>>(
            gxr, wqkvT_l, bq_l, bk_l, bv_l, nullptr, gqkv, 1536, 512, 512, 512, 0, 0, 0);

        // Scores = Q K^T (batched over B*H)
        mma_gemm<128,128,true,M_SCORES><<<gScore, 128, SM_T>>>(
            gq, gk, nullptr, nullptr, nullptr, nullptr, gsc, S_, DH_, DH_, DH_,
            (long)S_ * DH_, (long)S_ * DH_, (long)S_ * S_);

        softmax_k<<<B_ * H_ * S_, 256>>>(gsc);

        // Attn = P V (batched), write [B,S,D] rounded
        mma_gemm<128,64,false,M_PV><<<gPV, 128, SM_PV>>>(
            gsc, gv, nullptr, nullptr, nullptr, nullptr, gattn, DH_, S_, S_, DH_,
            (long)S_ * S_, (long)S_ * DH_, 0);

        // O projection + bias + residual
        mma_gemm<128,128,true,M_RES><<<gOP, 128, SM_T>>>(
            gattn, woT_l, bo_l, nullptr, nullptr, gx, gtmp, 512, 512, 512, 512, 0, 0, 0);
        ln_k<<<M_ROWS, 128>>>(gtmp, g1_l, be1_l, gx, gxr);

        // FFN1 + GELU (rounded out)
        mma_gemm<128,128,true,M_GELU><<<gF1, 128, SM_T>>>(
            gxr, w1T_l, b1_l, nullptr, nullptr, nullptr, gffn, 2048, 512, 512, 512, 0, 0, 0);
        // FFN2 + bias + residual
        mma_gemm<128,128,true,M_RES><<<gOP, 128, SM_T>>>(
            gffn, w2T_l, b2_l, nullptr, nullptr, gx, gtmp, 512, 2048, 2048, 2048, 0, 0, 0);
        ln_k<<<M_ROWS, 128>>>(gtmp, g2_l, be2_l,
                              (l == L_ - 1) ? (float*)d_out : gx, gxr);
    }
}

// round 6
// speedup vs baseline: 4.2605x; 1.2306x over previous
#include <cuda_runtime.h>
#include <math.h>
#include <stdint.h>

// Problem constants
static constexpr int B_ = 4, S_ = 1024, D_ = 512, H_ = 8, F_ = 2048, DH_ = 64, L_ = 8;
static constexpr int M_ROWS = B_ * S_;           // 4096
static constexpr float QK_SCALE = 0.125f;        // 1/sqrt(64)
static constexpr float LN_EPS = 1e-5f;

static constexpr long MD = (long)M_ROWS * D_;
// transposed+rounded weight slabs: [N,K] row-major per layer
static constexpr long SZ_QKV = 1536L * 512, SZ_O = 512L * 512, SZ_1 = 2048L * 512, SZ_2 = 512L * 2048;
static constexpr long OFF_TQKV = 0, OFF_TO = 8 * SZ_QKV, OFF_T1 = OFF_TO + 8 * SZ_O, OFF_T2 = OFF_T1 + 8 * SZ_1;

// Scratch (device globals; no allocation anywhere)
__device__ float g_x[M_ROWS * D_];        // exact fp32 residual stream
__device__ float g_xr[M_ROWS * D_];       // tf32-rounded copy for GEMM A
__device__ float g_qkv[3 * M_ROWS * D_];  // q/k/v slabs [B,H,S,DH], rounded
__device__ float g_attn[M_ROWS * D_];     // rounded
__device__ float g_tmp[M_ROWS * D_];
__device__ float g_ffn[M_ROWS * F_];      // rounded
__device__ float g_wT[8 * (SZ_QKV + SZ_O + SZ_1 + SZ_2)];  // ~101 MB

enum { M_RES = 2, M_GELU = 3, M_QKV = 6 };

// ---------------------------------------------------------------------------
// helpers
// ---------------------------------------------------------------------------
__device__ __forceinline__ uint32_t f2tf(float x) {
    uint32_t r;
    asm("cvt.rna.tf32.f32 %0, %1;" : "=r"(r) : "f"(x));
    return r;
}
__device__ __forceinline__ float frnd(float x) { return __uint_as_float(f2tf(x)); }

__device__ __forceinline__ void cpa16(uint32_t smem, const void* gptr) {
    asm volatile("cp.async.cg.shared.global [%0], [%1], 16;\n" :: "r"(smem), "l"(gptr));
}
__device__ __forceinline__ void cp_commit() {
    asm volatile("cp.async.commit_group;\n" ::);
}
template <int N>
__device__ __forceinline__ void cp_wait() {
    asm volatile("cp.async.wait_group %0;\n" :: "n"(N));
}
__device__ __forceinline__ uint32_t smem_u32(const void* p) {
    return (uint32_t)__cvta_generic_to_shared(p);
}

__device__ __forceinline__ void mma8(float* c, const uint32_t* a, const uint32_t* b) {
    asm("mma.sync.aligned.m16n8k8.row.col.f32.tf32.tf32.f32 "
        "{%0,%1,%2,%3}, {%4,%5,%6,%7}, {%8,%9}, {%0,%1,%2,%3};"
        : "+f"(c[0]), "+f"(c[1]), "+f"(c[2]), "+f"(c[3])
        : "r"(a[0]), "r"(a[1]), "r"(a[2]), "r"(a[3]), "r"(b[0]), "r"(b[1]));
}

// ---------------------------------------------------------------------------
// tf32 mma.sync GEMM: 128 threads, 4 warps of 64xWN, BK=32, 3-stage cp.async.
// C[m,n] = A[m,k] * Bt[n,k]^T, all operands pre-rounded tf32.
// ---------------------------------------------------------------------------
template <int BM, int BN>
static constexpr int smem_bytes() {
    return 3 * (BM * 36 + BN * 36) * 4;
}

template <int BM, int BN, int MODE>
__global__ __launch_bounds__(128)
void mma_gemm(const float* __restrict__ A, const float* __restrict__ Bm,
              const float* __restrict__ b0, const float* __restrict__ b1,
              const float* __restrict__ b2, const float* __restrict__ res,
              float* __restrict__ C, int N, int K)
{
    constexpr int BK = 32;
    constexpr int WM = 64, WN = BN / 2;
    constexpr int MI = WM / 16, NI = WN / 8;
    constexpr int ASTR = BK + 4;
    constexpr int ASZ = BM * ASTR;
    constexpr int BSZ = BN * ASTR;

    extern __shared__ float sm[];
    float* As = sm;
    float* Bs = sm + 3 * ASZ;

    const int bm = blockIdx.y * BM;
    const int bn = blockIdx.x * BN;
    const int tid = threadIdx.x;
    const int lane = tid & 31;
    const int warp = tid >> 5;
    const int wm0 = (warp >> 1) * WM;
    const int wn0 = (warp & 1) * WN;
    const int lr = lane >> 2;
    const int lc = lane & 3;

    float acc[MI][NI][4];
    #pragma unroll
    for (int i = 0; i < MI; i++)
        #pragma unroll
        for (int j = 0; j < NI; j++)
            #pragma unroll
            for (int q = 0; q < 4; q++) acc[i][j][q] = 0.0f;

    auto load_stage = [&](int j) {
        const int st = j % 3;
        float* as = As + st * ASZ;
        #pragma unroll
        for (int c = tid; c < BM * 8; c += 128) {
            int r = c >> 3, q = c & 7;
            cpa16(smem_u32(as + r * ASTR + q * 4),
                  A + (long)(bm + r) * K + j * BK + q * 4);
        }
        float* bs = Bs + st * BSZ;
        #pragma unroll
        for (int c = tid; c < BN * 8; c += 128) {
            int r = c >> 3, q = c & 7;
            cpa16(smem_u32(bs + r * ASTR + q * 4),
                  Bm + (long)(bn + r) * K + j * BK + q * 4);
        }
        cp_commit();
    };

    const int NIT = K / BK;
    load_stage(0);
    if (NIT > 1) load_stage(1);

    for (int it = 0; it < NIT; it++) {
        if (it + 2 < NIT) { load_stage(it + 2); cp_wait<2>(); }
        else if (it + 2 == NIT) { cp_wait<1>(); }
        else { cp_wait<0>(); }
        __syncthreads();

        const int st = it % 3;
        const float* as = As + st * ASZ;
        const float* bs = Bs + st * BSZ;
        #pragma unroll
        for (int kk = 0; kk < BK; kk += 8) {
            uint32_t af[MI][4];
            #pragma unroll
            for (int mi = 0; mi < MI; mi++) {
                const float* ap = as + (wm0 + mi * 16 + lr) * ASTR + kk + lc;
                af[mi][0] = __float_as_uint(ap[0]);
                af[mi][1] = __float_as_uint(ap[8 * ASTR]);
                af[mi][2] = __float_as_uint(ap[4]);
                af[mi][3] = __float_as_uint(ap[8 * ASTR + 4]);
            }
            uint32_t bf[NI][2];
            #pragma unroll
            for (int ni = 0; ni < NI; ni++) {
                const float* bp = bs + (wn0 + ni * 8 + lr) * ASTR + kk + lc;
                bf[ni][0] = __float_as_uint(bp[0]);
                bf[ni][1] = __float_as_uint(bp[4]);
            }
            #pragma unroll
            for (int mi = 0; mi < MI; mi++)
                #pragma unroll
                for (int ni = 0; ni < NI; ni++)
                    mma8(acc[mi][ni], af[mi], bf[ni]);
        }
        __syncthreads();
    }

    #pragma unroll
    for (int mi = 0; mi < MI; mi++) {
        #pragma unroll
        for (int ni = 0; ni < NI; ni++) {
            #pragma unroll
            for (int ri = 0; ri < 2; ri++) {
                const int m = bm + wm0 + mi * 16 + lr + ri * 8;
                const int n = bn + wn0 + ni * 8 + lc * 2;
                float v0 = acc[mi][ni][ri * 2 + 0];
                float v1 = acc[mi][ni][ri * 2 + 1];
                if (MODE == M_RES) {
                    long o = (long)m * N + n;
                    C[o]     = v0 + b0[n]     + res[o];
                    C[o + 1] = v1 + b0[n + 1] + res[o + 1];
                } else if (MODE == M_GELU) {
                    v0 += b0[n]; v1 += b0[n + 1];
                    long o = (long)m * N + n;
                    C[o]     = frnd(0.5f * v0 * (1.0f + erff(v0 * 0.70710678118654752f)));
                    C[o + 1] = frnd(0.5f * v1 * (1.0f + erff(v1 * 0.70710678118654752f)));
                } else { // M_QKV
                    const int t = n >> 9;
                    const int colD = n & 511;
                    const float* bb = (t == 0) ? b0 : ((t == 1) ? b1 : b2);
                    const float sc = (t == 0) ? QK_SCALE : 1.0f;
                    const int b = m >> 10, s = m & 1023, h = colD >> 6, dh0 = colD & 63;
                    long o = (long)t * MD + (((long)((b << 3) + h) * S_ + s) << 6) + dh0;
                    C[o]     = frnd((v0 + bb[colD]) * sc);
                    C[o + 1] = frnd((v1 + bb[colD + 1]) * sc);
                }
            }
        }
    }
}

// ---------------------------------------------------------------------------
// Flash attention: one CTA per (q-tile of 128, b*h). 256 threads, 8 warps.
// Q/K/V slabs [B,H,S,DH], tf32-pre-rounded, Q pre-scaled. Online softmax.
// ---------------------------------------------------------------------------
static constexpr int FA_KSTR = 68, FA_VSTR = 72;
static constexpr int FA_KSZ = 128 * FA_KSTR;       // 8704 floats
static constexpr int FA_VSZ = 128 * FA_VSTR;       // 9216 floats
static constexpr int FA_STAGE = FA_KSZ + FA_VSZ;   // 17920 floats
static constexpr int FA_PSTR = 132;
static constexpr int FA_PWARP = 16 * FA_PSTR;      // 2112 floats
static constexpr int FA_SMEM = (2 * FA_STAGE + 8 * FA_PWARP) * 4;  // 210944 B

__global__ __launch_bounds__(256)
void flash_k(const float* __restrict__ Q, const float* __restrict__ Kt,
             const float* __restrict__ V, float* __restrict__ O)
{
    extern __shared__ float sm[];
    float* kv = sm;
    float* pb = sm + 2 * FA_STAGE;

    const int bh = blockIdx.y;
    const int qt = blockIdx.x;
    const int tid = threadIdx.x, lane = tid & 31, w = tid >> 5;
    const int lr = lane >> 2, lc = lane & 3;
    const long base = (long)bh * S_ * DH_;

    auto loadkv = [&](int j) {
        float* ks = kv + (j & 1) * FA_STAGE;
        float* vs = ks + FA_KSZ;
        const float* kg = Kt + base + (long)j * 128 * 64;
        const float* vg = V  + base + (long)j * 128 * 64;
        #pragma unroll
        for (int c = tid; c < 2048; c += 256) {
            int r = c >> 4, q = (c & 15) * 4;
            cpa16(smem_u32(ks + r * FA_KSTR + q), kg + r * 64 + q);
            cpa16(smem_u32(vs + r * FA_VSTR + q), vg + r * 64 + q);
        }
        cp_commit();
    };

    loadkv(0);

    // Stage Q tile into P region, read fragments into registers.
    {
        const float* qg = Q + base + (long)qt * 128 * 64;
        #pragma unroll
        for (int c = tid; c < 2048; c += 256) {
            int r = c >> 4, q = (c & 15) * 4;
            *(float4*)(pb + r * FA_KSTR + q) = *(const float4*)(qg + r * 64 + q);
        }
    }
    __syncthreads();
    uint32_t qf[8][4];
    {
        const float* q0 = pb + (w * 16 + lr) * FA_KSTR;
        const float* q1 = pb + (w * 16 + lr + 8) * FA_KSTR;
        #pragma unroll
        for (int kk = 0; kk < 8; kk++) {
            qf[kk][0] = __float_as_uint(q0[kk * 8 + lc]);
            qf[kk][1] = __float_as_uint(q1[kk * 8 + lc]);
            qf[kk][2] = __float_as_uint(q0[kk * 8 + lc + 4]);
            qf[kk][3] = __float_as_uint(q1[kk * 8 + lc + 4]);
        }
    }

    float m0 = -1e30f, m1 = -1e30f, l0 = 0.0f, l1 = 0.0f;
    float oacc[8][4] = {};
    float* pw = pb + w * FA_PWARP;

    for (int j = 0; j < 8; j++) {
        if (j + 1 < 8) { loadkv(j + 1); cp_wait<1>(); }
        else           { cp_wait<0>(); }
        __syncthreads();   // stage j ready; also protects P region reuse

        const float* ks = kv + (j & 1) * FA_STAGE;
        const float* vs = ks + FA_KSZ;

        // S = Q K^T  (16 rows x 128 cols per warp)
        float sacc[16][4];
        #pragma unroll
        for (int ni = 0; ni < 16; ni++)
            #pragma unroll
            for (int q = 0; q < 4; q++) sacc[ni][q] = 0.0f;
        #pragma unroll
        for (int kk = 0; kk < 8; kk++) {
            #pragma unroll
            for (int ni = 0; ni < 16; ni++) {
                uint32_t bf[2];
                const float* bp = ks + (ni * 8 + lr) * FA_KSTR + kk * 8 + lc;
                bf[0] = __float_as_uint(bp[0]);
                bf[1] = __float_as_uint(bp[4]);
                mma8(sacc[ni], qf[kk], bf);
            }
        }

        // online softmax
        float mx0 = -1e30f, mx1 = -1e30f;
        #pragma unroll
        for (int ni = 0; ni < 16; ni++) {
            mx0 = fmaxf(mx0, fmaxf(sacc[ni][0], sacc[ni][1]));
            mx1 = fmaxf(mx1, fmaxf(sacc[ni][2], sacc[ni][3]));
        }
        mx0 = fmaxf(mx0, __shfl_xor_sync(0xFFFFFFFFu, mx0, 1));
        mx0 = fmaxf(mx0, __shfl_xor_sync(0xFFFFFFFFu, mx0, 2));
        mx1 = fmaxf(mx1, __shfl_xor_sync(0xFFFFFFFFu, mx1, 1));
        mx1 = fmaxf(mx1, __shfl_xor_sync(0xFFFFFFFFu, mx1, 2));
        const float mn0 = fmaxf(m0, mx0), mn1 = fmaxf(m1, mx1);
        const float al0 = expf(m0 - mn0), al1 = expf(m1 - mn1);

        float rs0 = 0.0f, rs1 = 0.0f;
        #pragma unroll
        for (int ni = 0; ni < 16; ni++) {
            float p0 = expf(sacc[ni][0] - mn0);
            float p1 = expf(sacc[ni][1] - mn0);
            float p2 = expf(sacc[ni][2] - mn1);
            float p3 = expf(sacc[ni][3] - mn1);
            rs0 += p0 + p1; rs1 += p2 + p3;
            const int col = ni * 8 + 2 * lc;
            pw[lr * FA_PSTR + col]           = frnd(p0);
            pw[lr * FA_PSTR + col + 1]       = frnd(p1);
            pw[(lr + 8) * FA_PSTR + col]     = frnd(p2);
            pw[(lr + 8) * FA_PSTR + col + 1] = frnd(p3);
        }
        rs0 += __shfl_xor_sync(0xFFFFFFFFu, rs0, 1);
        rs0 += __shfl_xor_sync(0xFFFFFFFFu, rs0, 2);
        rs1 += __shfl_xor_sync(0xFFFFFFFFu, rs1, 1);
        rs1 += __shfl_xor_sync(0xFFFFFFFFu, rs1, 2);
        m0 = mn0; m1 = mn1;
        l0 = l0 * al0 + rs0;
        l1 = l1 * al1 + rs1;
        #pragma unroll
        for (int ni = 0; ni < 8; ni++) {
            oacc[ni][0] *= al0; oacc[ni][1] *= al0;
            oacc[ni][2] *= al1; oacc[ni][3] *= al1;
        }
        __syncwarp();

        // O += P V  (P: 16x128, V: 128x64)
        #pragma unroll
        for (int kk2 = 0; kk2 < 16; kk2++) {
            uint32_t af[4];
            af[0] = __float_as_uint(pw[lr * FA_PSTR + kk2 * 8 + lc]);
            af[1] = __float_as_uint(pw[(lr + 8) * FA_PSTR + kk2 * 8 + lc]);
            af[2] = __float_as_uint(pw[lr * FA_PSTR + kk2 * 8 + lc + 4]);
            af[3] = __float_as_uint(pw[(lr + 8) * FA_PSTR + kk2 * 8 + lc + 4]);
            #pragma unroll
            for (int ni = 0; ni < 8; ni++) {
                uint32_t bf[2];
                const float* vp = vs + (kk2 * 8 + lc) * FA_VSTR + ni * 8 + lr;
                bf[0] = __float_as_uint(vp[0]);
                bf[1] = __float_as_uint(vp[4 * FA_VSTR]);
                mma8(oacc[ni], af, bf);
            }
        }
        __syncthreads();  // before next loadkv overwrites a stage
    }

    // epilogue: divide by l, write [B,S,D] rounded
    const float inv0 = 1.0f / l0, inv1 = 1.0f / l1;
    const int b = bh >> 3, h = bh & 7;
    const int r0 = qt * 128 + w * 16 + lr;
    #pragma unroll
    for (int ni = 0; ni < 8; ni++) {
        const int n = h * 64 + ni * 8 + 2 * lc;
        long o0 = ((long)(b * S_ + r0)) * D_ + n;
        long o1 = ((long)(b * S_ + r0 + 8)) * D_ + n;
        O[o0]     = frnd(oacc[ni][0] * inv0);
        O[o0 + 1] = frnd(oacc[ni][1] * inv0);
        O[o1]     = frnd(oacc[ni][2] * inv1);
        O[o1 + 1] = frnd(oacc[ni][3] * inv1);
    }
}

// ---------------------------------------------------------------------------
// transpose + tf32-round weights: out[n*K+k] = rna(in[k*N+n]), per layer z
// ---------------------------------------------------------------------------
__global__ __launch_bounds__(256) void transpose_round(
    const float* __restrict__ in, float* __restrict__ out,
    int K, int N, long in_ls, long out_ls)
{
    __shared__ float t[32][33];
    in  += (long)blockIdx.z * in_ls;
    out += (long)blockIdx.z * out_ls;
    const int k0 = blockIdx.y * 32, n0 = blockIdx.x * 32;
    #pragma unroll
    for (int i = threadIdx.y; i < 32; i += 8)
        t[i][threadIdx.x] = in[(long)(k0 + i) * N + n0 + threadIdx.x];
    __syncthreads();
    #pragma unroll
    for (int i = threadIdx.y; i < 32; i += 8)
        out[(long)(n0 + i) * K + k0 + threadIdx.x] = frnd(t[threadIdx.x][i]);
}

// copy x -> gx (exact) and gxr (rounded)
__global__ __launch_bounds__(256) void copyround_k(const float* __restrict__ x,
                                                   float* __restrict__ gx,
                                                   float* __restrict__ gxr, int n4)
{
    int i = blockIdx.x * blockDim.x + threadIdx.x;
    int stride = gridDim.x * blockDim.x;
    const float4* in4 = reinterpret_cast<const float4*>(x);
    for (; i < n4; i += stride) {
        float4 v = in4[i];
        reinterpret_cast<float4*>(gx)[i] = v;
        v.x = frnd(v.x); v.y = frnd(v.y); v.z = frnd(v.z); v.w = frnd(v.w);
        reinterpret_cast<float4*>(gxr)[i] = v;
    }
}

// ---------------------------------------------------------------------------
// Row LayerNorm over 512 elements; exact out + rounded out_r.
// ---------------------------------------------------------------------------
__global__ __launch_bounds__(128) void ln_k(const float* __restrict__ in,
                                            const float* __restrict__ g,
                                            const float* __restrict__ be,
                                            float* __restrict__ out,
                                            float* __restrict__ out_r)
{
    const int row = blockIdx.x;
    const int t = threadIdx.x;
    const float4 v = reinterpret_cast<const float4*>(in + (long)row * D_)[t];

    float s  = v.x + v.y + v.z + v.w;
    float sq = v.x * v.x + v.y * v.y + v.z * v.z + v.w * v.w;
    #pragma unroll
    for (int o = 16; o; o >>= 1) {
        s  += __shfl_xor_sync(0xFFFFFFFFu, s, o);
        sq += __shfl_xor_sync(0xFFFFFFFFu, sq, o);
    }
    __shared__ float sh0[4], sh1[4];
    if ((t & 31) == 0) { sh0[t >> 5] = s; sh1[t >> 5] = sq; }
    __syncthreads();
    s  = sh0[0] + sh0[1] + sh0[2] + sh0[3];
    sq = sh1[0] + sh1[1] + sh1[2] + sh1[3];

    const float mean = s * (1.0f / D_);
    const float var  = sq * (1.0f / D_) - mean * mean;
    const float inv  = rsqrtf(var + LN_EPS);

    const float4 gg = reinterpret_cast<const float4*>(g)[t];
    const float4 bb = reinterpret_cast<const float4*>(be)[t];
    float4 o4;
    o4.x = (v.x - mean) * inv * gg.x + bb.x;
    o4.y = (v.y - mean) * inv * gg.y + bb.y;
    o4.z = (v.z - mean) * inv * gg.z + bb.z;
    o4.w = (v.w - mean) * inv * gg.w + bb.w;
    reinterpret_cast<float4*>(out + (long)row * D_)[t] = o4;
    if (out_r) {
        float4 r4;
        r4.x = frnd(o4.x); r4.y = frnd(o4.y); r4.z = frnd(o4.z); r4.w = frnd(o4.w);
        reinterpret_cast<float4*>(out_r + (long)row * D_)[t] = r4;
    }
}

// ---------------------------------------------------------------------------
// Host driver
// ---------------------------------------------------------------------------
extern "C" void kernel_launch(void* const* d_in, const int* in_sizes, int n_in,
                              void* d_out, int out_size)
{
    const float* x   = (const float*)d_in[0];
    const float* wq  = (const float*)d_in[1];
    const float* bq  = (const float*)d_in[2];
    const float* wk  = (const float*)d_in[3];
    const float* bk  = (const float*)d_in[4];
    const float* wv  = (const float*)d_in[5];
    const float* bv  = (const float*)d_in[6];
    const float* wo  = (const float*)d_in[7];
    const float* bo  = (const float*)d_in[8];
    const float* g1  = (const float*)d_in[9];
    const float* be1 = (const float*)d_in[10];
    const float* w1  = (const float*)d_in[11];
    const float* b1  = (const float*)d_in[12];
    const float* w2  = (const float*)d_in[13];
    const float* b2  = (const float*)d_in[14];
    const float* g2  = (const float*)d_in[15];
    const float* be2 = (const float*)d_in[16];

    float *gx, *gxr, *gqkv, *gattn, *gtmp, *gffn, *gwT;
    cudaGetSymbolAddress((void**)&gx,    g_x);
    cudaGetSymbolAddress((void**)&gxr,   g_xr);
    cudaGetSymbolAddress((void**)&gqkv,  g_qkv);
    cudaGetSymbolAddress((void**)&gattn, g_attn);
    cudaGetSymbolAddress((void**)&gtmp,  g_tmp);
    cudaGetSymbolAddress((void**)&gffn,  g_ffn);
    cudaGetSymbolAddress((void**)&gwT,   g_wT);

    constexpr int SM_T = smem_bytes<128, 128>();   // 110592
    (void)cudaFuncSetAttribute(mma_gemm<128,128,M_QKV>,  cudaFuncAttributeMaxDynamicSharedMemorySize, SM_T);
    (void)cudaFuncSetAttribute(mma_gemm<128,128,M_RES>,  cudaFuncAttributeMaxDynamicSharedMemorySize, SM_T);
    (void)cudaFuncSetAttribute(mma_gemm<128,128,M_GELU>, cudaFuncAttributeMaxDynamicSharedMemorySize, SM_T);
    (void)cudaFuncSetAttribute(flash_k, cudaFuncAttributeMaxDynamicSharedMemorySize, FA_SMEM);

    copyround_k<<<512, 256>>>(x, gx, gxr, M_ROWS * D_ / 4);

    // transpose + round weights into [N,K] slabs
    const dim3 tb(32, 8);
    transpose_round<<<dim3(16, 16, 8), tb>>>(wq, gwT + OFF_TQKV,            512, 512,  (long)D_*D_, SZ_QKV);
    transpose_round<<<dim3(16, 16, 8), tb>>>(wk, gwT + OFF_TQKV + 512*512,  512, 512,  (long)D_*D_, SZ_QKV);
    transpose_round<<<dim3(16, 16, 8), tb>>>(wv, gwT + OFF_TQKV + 1024*512, 512, 512,  (long)D_*D_, SZ_QKV);
    transpose_round<<<dim3(16, 16, 8), tb>>>(wo, gwT + OFF_TO,              512, 512,  (long)D_*D_, SZ_O);
    transpose_round<<<dim3(64, 16, 8), tb>>>(w1, gwT + OFF_T1,              512, 2048, (long)D_*F_, SZ_1);
    transpose_round<<<dim3(16, 64, 8), tb>>>(w2, gwT + OFF_T2,              2048, 512, (long)F_*D_, SZ_2);

    float* gq = gqkv;
    float* gk = gqkv + MD;
    float* gv = gqkv + 2 * MD;

    const dim3 gQKV(1536 / 128, M_ROWS / 128);   // (12, 32)
    const dim3 gOP(512 / 128, M_ROWS / 128);     // (4, 32)
    const dim3 gF1(2048 / 128, M_ROWS / 128);    // (16, 32)
    const dim3 gFA(S_ / 128, B_ * H_);           // (8, 32)

    for (int l = 0; l < L_; l++) {
        const float* wqkvT_l = gwT + OFF_TQKV + (long)l * SZ_QKV;
        const float* woT_l   = gwT + OFF_TO   + (long)l * SZ_O;
        const float* w1T_l   = gwT + OFF_T1   + (long)l * SZ_1;
        const float* w2T_l   = gwT + OFF_T2   + (long)l * SZ_2;
        const float* bq_l = bq + (long)l * D_;
        const float* bk_l = bk + (long)l * D_;
        const float* bv_l = bv + (long)l * D_;
        const float* bo_l = bo + (long)l * D_;
        const float* b1_l = b1 + (long)l * F_;
        const float* b2_l = b2 + (long)l * D_;
        const float* g1_l = g1 + (long)l * D_;
        const float* g2_l = g2 + (long)l * D_;
        const float* be1_l = be1 + (long)l * D_;
        const float* be2_l = be2 + (long)l * D_;

        // fused QKV projection -> q/k/v slabs [B,H,S,DH], rounded, Q pre-scaled
        mma_gemm<128,128,M_QKV><<<gQKV, 128, SM_T>>>(
            gxr, wqkvT_l, bq_l, bk_l, bv_l, nullptr, gqkv, 1536, 512);

        // fused attention (scores + softmax + PV)
        flash_k<<<gFA, 256, FA_SMEM>>>(gq, gk, gv, gattn);

        // O projection + bias + residual
        mma_gemm<128,128,M_RES><<<gOP, 128, SM_T>>>(
            gattn, woT_l, bo_l, nullptr, nullptr, gx, gtmp, 512, 512);
        ln_k<<<M_ROWS, 128>>>(gtmp, g1_l, be1_l, gx, gxr);

        // FFN1 + GELU (rounded out)
        mma_gemm<128,128,M_GELU><<<gF1, 128, SM_T>>>(
            gxr, w1T_l, b1_l, nullptr, nullptr, nullptr, gffn, 2048, 512);
        // FFN2 + bias + residual
        mma_gemm<128,128,M_RES><<<gOP, 128, SM_T>>>(
            gffn, w2T_l, b2_l, nullptr, nullptr, gx, gtmp, 512, 2048);
        ln_k<<<M_ROWS, 128>>>(gtmp, g2_l, be2_l,
                              (l == L_ - 1) ? (float*)d_out : gx, gxr);
    }
}

// round 7
// speedup vs baseline: 6.3937x; 1.5007x over previous
#include <cuda_runtime.h>
#include <cuda_fp16.h>
#include <math.h>
#include <stdint.h>

// Problem constants
static constexpr int B_ = 4, S_ = 1024, D_ = 512, H_ = 8, F_ = 2048, DH_ = 64, L_ = 8;
static constexpr int M_ROWS = B_ * S_;           // 4096
static constexpr float QK_SCALE = 0.125f;        // 1/sqrt(64)
static constexpr float LN_EPS = 1e-5f;

static constexpr long MD = (long)M_ROWS * D_;    // 2097152
// transposed half weight slabs: [N,K] row-major per layer
static constexpr long SZ_QKV = 1536L * 512, SZ_O = 512L * 512, SZ_1 = 2048L * 512, SZ_2 = 512L * 2048;
static constexpr long OFF_TQKV = 0, OFF_TO = 8 * SZ_QKV, OFF_T1 = OFF_TO + 8 * SZ_O, OFF_T2 = OFF_T1 + 8 * SZ_1;

// Scratch (device globals; no allocation anywhere)
__device__ float g_x[M_ROWS * D_];                          // exact fp32 residual stream
__device__ __align__(16) __half g_xh[M_ROWS * D_];          // half copy for GEMM A
__device__ __align__(16) __half g_qkv[3 * M_ROWS * D_];     // q,k [B,H,S,DH]; vT [B,H,DH,S]
__device__ __align__(16) __half g_attn[M_ROWS * D_];
__device__ float g_tmp[M_ROWS * D_];
__device__ __align__(16) __half g_ffn[M_ROWS * F_];
__device__ __align__(16) __half g_wH[8 * (SZ_QKV + SZ_O + SZ_1 + SZ_2)];   // ~50 MB

enum { M_RES = 2, M_GELU = 3, M_QKV = 6 };

// ---------------------------------------------------------------------------
// helpers
// ---------------------------------------------------------------------------
__device__ __forceinline__ void cpa16(uint32_t smem, const void* gptr) {
    asm volatile("cp.async.cg.shared.global [%0], [%1], 16;\n" :: "r"(smem), "l"(gptr));
}
__device__ __forceinline__ void cp_commit() {
    asm volatile("cp.async.commit_group;\n" ::);
}
template <int N>
__device__ __forceinline__ void cp_wait() {
    asm volatile("cp.async.wait_group %0;\n" :: "n"(N));
}
__device__ __forceinline__ uint32_t smem_u32(const void* p) {
    return (uint32_t)__cvta_generic_to_shared(p);
}
__device__ __forceinline__ uint32_t ldh2(const __half* p) {
    return *reinterpret_cast<const uint32_t*>(p);
}

// m16n8k16 f16 mma, fp32 accumulate
__device__ __forceinline__ void mma16(float* c, const uint32_t* a, const uint32_t* b) {
    asm("mma.sync.aligned.m16n8k16.row.col.f32.f16.f16.f32 "
        "{%0,%1,%2,%3}, {%4,%5,%6,%7}, {%8,%9}, {%0,%1,%2,%3};"
        : "+f"(c[0]), "+f"(c[1]), "+f"(c[2]), "+f"(c[3])
        : "r"(a[0]), "r"(a[1]), "r"(a[2]), "r"(a[3]), "r"(b[0]), "r"(b[1]));
}

// ---------------------------------------------------------------------------
// fp16 mma GEMM: 128 threads, 4 warps of 64x(BN/2), BK=32, 3-stage cp.async.
// C[m,n] = A[m,k] (half, row-major) * Bt[n,k] (half, row-major)^T
// A-frag layout (m16n8k16): a0=(lr,2lc) a1=(lr+8,2lc) a2=(lr,2lc+8) a3=(lr+8,2lc+8)
// B-frag: b0=(k=2lc,n=lr) b1=(k=2lc+8,n=lr) — from [n][k] storage: half2 loads.
// ---------------------------------------------------------------------------
static constexpr int G_ASTR = 40;  // halfs per row (32 + 8 pad)
template <int BM, int BN>
static constexpr int smem_bytes() { return 3 * (BM + BN) * G_ASTR * 2; }

template <int BM, int BN, int MODE>
__global__ __launch_bounds__(128)
void mma_gemm(const __half* __restrict__ A, const __half* __restrict__ Bm,
              const float* __restrict__ b0, const float* __restrict__ b1,
              const float* __restrict__ b2, const float* __restrict__ res,
              float* __restrict__ Cf, __half* __restrict__ Ch, int N, int K)
{
    constexpr int BK = 32;
    constexpr int WM = 64, WN = BN / 2;
    constexpr int MI = WM / 16, NI = WN / 8;     // 4, (8|4)
    constexpr int ASZ = BM * G_ASTR;             // halfs per A stage
    constexpr int BSZ = BN * G_ASTR;

    extern __shared__ __align__(16) __half smh[];
    __half* As = smh;
    __half* Bs = smh + 3 * ASZ;

    const int bm = blockIdx.y * BM;
    const int bn = blockIdx.x * BN;
    const int tid = threadIdx.x;
    const int lane = tid & 31;
    const int warp = tid >> 5;
    const int wm0 = (warp >> 1) * WM;
    const int wn0 = (warp & 1) * WN;
    const int lr = lane >> 2;
    const int lc = lane & 3;

    float acc[MI][NI][4];
    #pragma unroll
    for (int i = 0; i < MI; i++)
        #pragma unroll
        for (int j = 0; j < NI; j++)
            #pragma unroll
            for (int q = 0; q < 4; q++) acc[i][j][q] = 0.0f;

    auto load_stage = [&](int j) {
        const int st = j % 3;
        __half* as = As + st * ASZ;
        #pragma unroll
        for (int c = tid; c < BM * 4; c += 128) {
            int r = c >> 2, q = (c & 3) * 8;
            cpa16(smem_u32(as + r * G_ASTR + q), A + (long)(bm + r) * K + j * BK + q);
        }
        __half* bs = Bs + st * BSZ;
        #pragma unroll
        for (int c = tid; c < BN * 4; c += 128) {
            int r = c >> 2, q = (c & 3) * 8;
            cpa16(smem_u32(bs + r * G_ASTR + q), Bm + (long)(bn + r) * K + j * BK + q);
        }
        cp_commit();
    };

    const int NIT = K / BK;
    load_stage(0);
    if (NIT > 1) load_stage(1);

    for (int it = 0; it < NIT; it++) {
        if (it + 2 < NIT) { load_stage(it + 2); cp_wait<2>(); }
        else if (it + 2 == NIT) { cp_wait<1>(); }
        else { cp_wait<0>(); }
        __syncthreads();

        const int st = it % 3;
        const __half* as = As + st * ASZ;
        const __half* bs = Bs + st * BSZ;
        #pragma unroll
        for (int kk = 0; kk < BK; kk += 16) {
            uint32_t af[MI][4];
            #pragma unroll
            for (int mi = 0; mi < MI; mi++) {
                const __half* ap = as + (wm0 + mi * 16 + lr) * G_ASTR + kk + 2 * lc;
                af[mi][0] = ldh2(ap);
                af[mi][1] = ldh2(ap + 8 * G_ASTR);
                af[mi][2] = ldh2(ap + 8);
                af[mi][3] = ldh2(ap + 8 * G_ASTR + 8);
            }
            uint32_t bf[NI][2];
            #pragma unroll
            for (int ni = 0; ni < NI; ni++) {
                const __half* bp = bs + (wn0 + ni * 8 + lr) * G_ASTR + kk + 2 * lc;
                bf[ni][0] = ldh2(bp);
                bf[ni][1] = ldh2(bp + 8);
            }
            #pragma unroll
            for (int mi = 0; mi < MI; mi++)
                #pragma unroll
                for (int ni = 0; ni < NI; ni++)
                    mma16(acc[mi][ni], af[mi], bf[ni]);
        }
        __syncthreads();
    }

    // Epilogue (C layout identical to m16n8k8: c0,c1=(lr, 2lc,2lc+1), c2,c3=(lr+8,...))
    #pragma unroll
    for (int mi = 0; mi < MI; mi++) {
        #pragma unroll
        for (int ni = 0; ni < NI; ni++) {
            #pragma unroll
            for (int ri = 0; ri < 2; ri++) {
                const int m = bm + wm0 + mi * 16 + lr + ri * 8;
                const int n = bn + wn0 + ni * 8 + lc * 2;
                float v0 = acc[mi][ni][ri * 2 + 0];
                float v1 = acc[mi][ni][ri * 2 + 1];
                if (MODE == M_RES) {
                    long o = (long)m * N + n;
                    Cf[o]     = v0 + b0[n]     + res[o];
                    Cf[o + 1] = v1 + b0[n + 1] + res[o + 1];
                } else if (MODE == M_GELU) {
                    v0 += b0[n]; v1 += b0[n + 1];
                    float g0 = 0.5f * v0 * (1.0f + erff(v0 * 0.70710678118654752f));
                    float g1 = 0.5f * v1 * (1.0f + erff(v1 * 0.70710678118654752f));
                    *reinterpret_cast<__half2*>(Ch + (long)m * N + n) = __floats2half2_rn(g0, g1);
                } else { // M_QKV: n in [0,1536): q,k -> [B,H,S,DH]; v -> [B,H,DH,S]
                    const int t = n >> 9;
                    const int colD = n & 511;
                    const float* bb = (t == 0) ? b0 : ((t == 1) ? b1 : b2);
                    const int b = m >> 10, s = m & 1023, h = colD >> 6, dh0 = colD & 63;
                    const int bh = (b << 3) + h;
                    float u0 = v0 + bb[colD], u1 = v1 + bb[colD + 1];
                    if (t == 0) { u0 *= QK_SCALE; u1 *= QK_SCALE; }
                    if (t == 2) {
                        long o = 2 * MD + ((long)bh << 16) + ((long)dh0 << 10) + s;
                        Ch[o]        = __float2half_rn(u0);
                        Ch[o + 1024] = __float2half_rn(u1);
                    } else {
                        long o = (long)t * MD + (((long)bh * S_ + s) << 6) + dh0;
                        *reinterpret_cast<__half2*>(Ch + o) = __floats2half2_rn(u0, u1);
                    }
                }
            }
        }
    }
}

// ---------------------------------------------------------------------------
// Flash attention (fp16 operands): one CTA per (q-tile 128, b*h). 8 warps.
// Q,K: [B,H,S,DH] half (Q pre-scaled). Vt: [B,H,DH,S] half. Online softmax.
// ---------------------------------------------------------------------------
static constexpr int FA_KSTR = 72;                    // halfs (64 + 8 pad)
static constexpr int FA_VSTR = 136;                   // halfs (128 + 8 pad)
static constexpr int FA_KSZ = 128 * FA_KSTR;          // 9216 halfs
static constexpr int FA_VSZ = 64 * FA_VSTR;           // 8704 halfs
static constexpr int FA_STAGE = FA_KSZ + FA_VSZ;      // 17920 halfs
static constexpr int FA_PSTR = 136;
static constexpr int FA_PWARP = 16 * FA_PSTR;         // 2176 halfs
static constexpr int FA_SMEM = (2 * FA_STAGE + 8 * FA_PWARP) * 2;  // 106496 B

__global__ __launch_bounds__(256)
void flash_k(const __half* __restrict__ Q, const __half* __restrict__ Kt,
             const __half* __restrict__ Vt, __half* __restrict__ O)
{
    extern __shared__ __align__(16) __half smh[];
    __half* kv = smh;
    __half* pb = smh + 2 * FA_STAGE;

    const int bh = blockIdx.y;
    const int qt = blockIdx.x;
    const int tid = threadIdx.x, lane = tid & 31, w = tid >> 5;
    const int lr = lane >> 2, lc = lane & 3;
    const long base = (long)bh * S_ * DH_;   // same count for [s][dh] and [dh][s]

    auto loadkv = [&](int j) {
        __half* ks = kv + (j & 1) * FA_STAGE;
        __half* vs = ks + FA_KSZ;
        const __half* kg = Kt + base + (long)j * 128 * 64;   // rows of [s][dh]
        const __half* vg = Vt + base + (long)j * 128;        // col-slice of [dh][s=1024]
        #pragma unroll
        for (int c = tid; c < 1024; c += 256) {              // K: 128 rows x 8 chunks
            int r = c >> 3, q = (c & 7) * 8;
            cpa16(smem_u32(ks + r * FA_KSTR + q), kg + r * 64 + q);
        }
        #pragma unroll
        for (int c = tid; c < 1024; c += 256) {              // V: 64 rows x 16 chunks
            int r = c >> 4, q = (c & 15) * 8;
            cpa16(smem_u32(vs + r * FA_VSTR + q), vg + (long)r * 1024 + q);
        }
        cp_commit();
    };

    loadkv(0);

    // Stage Q tile into P region (128 x 64 halfs, stride FA_KSTR), grab fragments.
    {
        const __half* qg = Q + base + (long)qt * 128 * 64;
        #pragma unroll
        for (int c = tid; c < 1024; c += 256) {
            int r = c >> 3, q = (c & 7) * 8;
            *reinterpret_cast<uint4*>(pb + r * FA_KSTR + q) =
                *reinterpret_cast<const uint4*>(qg + r * 64 + q);
        }
    }
    __syncthreads();
    uint32_t qf[4][4];
    {
        const __half* q0 = pb + (w * 16 + lr) * FA_KSTR + 2 * lc;
        const __half* q1 = q0 + 8 * FA_KSTR;
        #pragma unroll
        for (int kk = 0; kk < 4; kk++) {
            qf[kk][0] = ldh2(q0 + kk * 16);
            qf[kk][1] = ldh2(q1 + kk * 16);
            qf[kk][2] = ldh2(q0 + kk * 16 + 8);
            qf[kk][3] = ldh2(q1 + kk * 16 + 8);
        }
    }

    float m0 = -1e30f, m1 = -1e30f, l0 = 0.0f, l1 = 0.0f;
    float oacc[8][4] = {};
    __half* pw = pb + w * FA_PWARP;

    for (int j = 0; j < 8; j++) {
        if (j + 1 < 8) { loadkv(j + 1); cp_wait<1>(); }
        else           { cp_wait<0>(); }
        __syncthreads();   // stage j ready; also protects P region reuse

        const __half* ks = kv + (j & 1) * FA_STAGE;
        const __half* vs = ks + FA_KSZ;

        // S = Q K^T (16 q-rows x 128 s-cols per warp); K smem [s][dh] = B [n][k]
        float sacc[16][4];
        #pragma unroll
        for (int ni = 0; ni < 16; ni++)
            #pragma unroll
            for (int q = 0; q < 4; q++) sacc[ni][q] = 0.0f;
        #pragma unroll
        for (int kk = 0; kk < 4; kk++) {
            #pragma unroll
            for (int ni = 0; ni < 16; ni++) {
                uint32_t bf[2];
                const __half* bp = ks + (ni * 8 + lr) * FA_KSTR + kk * 16 + 2 * lc;
                bf[0] = ldh2(bp);
                bf[1] = ldh2(bp + 8);
                mma16(sacc[ni], qf[kk], bf);
            }
        }

        // online softmax
        float mx0 = -1e30f, mx1 = -1e30f;
        #pragma unroll
        for (int ni = 0; ni < 16; ni++) {
            mx0 = fmaxf(mx0, fmaxf(sacc[ni][0], sacc[ni][1]));
            mx1 = fmaxf(mx1, fmaxf(sacc[ni][2], sacc[ni][3]));
        }
        mx0 = fmaxf(mx0, __shfl_xor_sync(0xFFFFFFFFu, mx0, 1));
        mx0 = fmaxf(mx0, __shfl_xor_sync(0xFFFFFFFFu, mx0, 2));
        mx1 = fmaxf(mx1, __shfl_xor_sync(0xFFFFFFFFu, mx1, 1));
        mx1 = fmaxf(mx1, __shfl_xor_sync(0xFFFFFFFFu, mx1, 2));
        const float mn0 = fmaxf(m0, mx0), mn1 = fmaxf(m1, mx1);
        const float al0 = expf(m0 - mn0), al1 = expf(m1 - mn1);

        float rs0 = 0.0f, rs1 = 0.0f;
        #pragma unroll
        for (int ni = 0; ni < 16; ni++) {
            float p0 = expf(sacc[ni][0] - mn0);
            float p1 = expf(sacc[ni][1] - mn0);
            float p2 = expf(sacc[ni][2] - mn1);
            float p3 = expf(sacc[ni][3] - mn1);
            rs0 += p0 + p1; rs1 += p2 + p3;
            const int col = ni * 8 + 2 * lc;
            *reinterpret_cast<__half2*>(pw + lr * FA_PSTR + col)       = __floats2half2_rn(p0, p1);
            *reinterpret_cast<__half2*>(pw + (lr + 8) * FA_PSTR + col) = __floats2half2_rn(p2, p3);
        }
        rs0 += __shfl_xor_sync(0xFFFFFFFFu, rs0, 1);
        rs0 += __shfl_xor_sync(0xFFFFFFFFu, rs0, 2);
        rs1 += __shfl_xor_sync(0xFFFFFFFFu, rs1, 1);
        rs1 += __shfl_xor_sync(0xFFFFFFFFu, rs1, 2);
        m0 = mn0; m1 = mn1;
        l0 = l0 * al0 + rs0;
        l1 = l1 * al1 + rs1;
        #pragma unroll
        for (int ni = 0; ni < 8; ni++) {
            oacc[ni][0] *= al0; oacc[ni][1] *= al0;
            oacc[ni][2] *= al1; oacc[ni][3] *= al1;
        }
        __syncwarp();

        // O += P V : P (16 x 128) A-operand from pw; Vt smem [dh][s] = B [n][k]
        #pragma unroll
        for (int kk2 = 0; kk2 < 8; kk2++) {
            uint32_t af[4];
            const __half* pp = pw + lr * FA_PSTR + kk2 * 16 + 2 * lc;
            af[0] = ldh2(pp);
            af[1] = ldh2(pp + 8 * FA_PSTR);
            af[2] = ldh2(pp + 8);
            af[3] = ldh2(pp + 8 * FA_PSTR + 8);
            #pragma unroll
            for (int ni = 0; ni < 8; ni++) {
                uint32_t bf[2];
                const __half* vp = vs + (ni * 8 + lr) * FA_VSTR + kk2 * 16 + 2 * lc;
                bf[0] = ldh2(vp);
                bf[1] = ldh2(vp + 8);
                mma16(oacc[ni], af, bf);
            }
        }
        __syncthreads();  // before next loadkv overwrites a stage
    }

    // epilogue: divide by l, write [B,S,D] half
    const float inv0 = 1.0f / l0, inv1 = 1.0f / l1;
    const int b = bh >> 3, h = bh & 7;
    const int r0 = qt * 128 + w * 16 + lr;
    #pragma unroll
    for (int ni = 0; ni < 8; ni++) {
        const int n = h * 64 + ni * 8 + 2 * lc;
        long o0 = ((long)(b * S_ + r0)) * D_ + n;
        long o1 = ((long)(b * S_ + r0 + 8)) * D_ + n;
        *reinterpret_cast<__half2*>(O + o0) = __floats2half2_rn(oacc[ni][0] * inv0, oacc[ni][1] * inv0);
        *reinterpret_cast<__half2*>(O + o1) = __floats2half2_rn(oacc[ni][2] * inv1, oacc[ni][3] * inv1);
    }
}

// ---------------------------------------------------------------------------
// Merged weight prep: transpose + fp16 convert all six weights in one launch.
// out_half[n*K + k] = (half) in_f32[k*N + n]
// ---------------------------------------------------------------------------
__global__ __launch_bounds__(256) void prep_all(
    const float* __restrict__ wq, const float* __restrict__ wk,
    const float* __restrict__ wv, const float* __restrict__ wo,
    const float* __restrict__ w1, const float* __restrict__ w2,
    __half* __restrict__ out)
{
    __shared__ float t[32][33];
    const int id = blockIdx.x;
    const float* src; __half* dst; int K, N, ki, ni;
    if (id < 8192) {                    // wq/wk/wv/wo: 4 x 8 layers x 256 tiles
        const int wsel = id >> 11, rem = id & 2047;
        const int layer = rem >> 8, tile = rem & 255;
        K = 512; N = 512; ki = tile >> 4; ni = tile & 15;
        src = (wsel == 0 ? wq : wsel == 1 ? wk : wsel == 2 ? wv : wo) + (long)layer * 262144;
        dst = out + (wsel < 3 ? OFF_TQKV + (long)layer * SZ_QKV + (long)wsel * 262144
                              : OFF_TO + (long)layer * SZ_O);
    } else if (id < 16384) {            // w1: 8 layers x 1024 tiles
        const int rem = id - 8192, layer = rem >> 10, tile = rem & 1023;
        K = 512; N = 2048; ki = tile >> 6; ni = tile & 63;
        src = w1 + (long)layer * 1048576;
        dst = out + OFF_T1 + (long)layer * SZ_1;
    } else {                            // w2: 8 layers x 1024 tiles
        const int rem = id - 16384, layer = rem >> 10, tile = rem & 1023;
        K = 2048; N = 512; ki = tile >> 4; ni = tile & 15;
        src = w2 + (long)layer * 1048576;
        dst = out + OFF_T2 + (long)layer * SZ_2;
    }
    const int k0 = ki * 32, n0 = ni * 32;
    #pragma unroll
    for (int i = threadIdx.y; i < 32; i += 8)
        t[i][threadIdx.x] = src[(long)(k0 + i) * N + n0 + threadIdx.x];
    __syncthreads();
    #pragma unroll
    for (int i = threadIdx.y; i < 32; i += 8)
        dst[(long)(n0 + i) * K + k0 + threadIdx.x] = __float2half_rn(t[threadIdx.x][i]);
}

// copy x -> gx (fp32) and gxh (half)
__global__ __launch_bounds__(256) void copy_half(const float* __restrict__ x,
                                                 float* __restrict__ gx,
                                                 __half* __restrict__ gxh, int n4)
{
    int i = blockIdx.x * blockDim.x + threadIdx.x;
    int stride = gridDim.x * blockDim.x;
    for (; i < n4; i += stride) {
        float4 v = reinterpret_cast<const float4*>(x)[i];
        reinterpret_cast<float4*>(gx)[i] = v;
        reinterpret_cast<__half2*>(gxh)[2 * i]     = __floats2half2_rn(v.x, v.y);
        reinterpret_cast<__half2*>(gxh)[2 * i + 1] = __floats2half2_rn(v.z, v.w);
    }
}

// ---------------------------------------------------------------------------
// Row LayerNorm over 512 elements; fp32 out + half out_h.
// ---------------------------------------------------------------------------
__global__ __launch_bounds__(128) void ln_k(const float* __restrict__ in,
                                            const float* __restrict__ g,
                                            const float* __restrict__ be,
                                            float* __restrict__ out,
                                            __half* __restrict__ out_h)
{
    const int row = blockIdx.x;
    const int t = threadIdx.x;
    const float4 v = reinterpret_cast<const float4*>(in + (long)row * D_)[t];

    float s  = v.x + v.y + v.z + v.w;
    float sq = v.x * v.x + v.y * v.y + v.z * v.z + v.w * v.w;
    #pragma unroll
    for (int o = 16; o; o >>= 1) {
        s  += __shfl_xor_sync(0xFFFFFFFFu, s, o);
        sq += __shfl_xor_sync(0xFFFFFFFFu, sq, o);
    }
    __shared__ float sh0[4], sh1[4];
    if ((t & 31) == 0) { sh0[t >> 5] = s; sh1[t >> 5] = sq; }
    __syncthreads();
    s  = sh0[0] + sh0[1] + sh0[2] + sh0[3];
    sq = sh1[0] + sh1[1] + sh1[2] + sh1[3];

    const float mean = s * (1.0f / D_);
    const float var  = sq * (1.0f / D_) - mean * mean;
    const float inv  = rsqrtf(var + LN_EPS);

    const float4 gg = reinterpret_cast<const float4*>(g)[t];
    const float4 bb = reinterpret_cast<const float4*>(be)[t];
    float4 o4;
    o4.x = (v.x - mean) * inv * gg.x + bb.x;
    o4.y = (v.y - mean) * inv * gg.y + bb.y;
    o4.z = (v.z - mean) * inv * gg.z + bb.z;
    o4.w = (v.w - mean) * inv * gg.w + bb.w;
    reinterpret_cast<float4*>(out + (long)row * D_)[t] = o4;
    __half2* oh = reinterpret_cast<__half2*>(out_h + (long)row * D_);
    oh[2 * t]     = __floats2half2_rn(o4.x, o4.y);
    oh[2 * t + 1] = __floats2half2_rn(o4.z, o4.w);
}

// ---------------------------------------------------------------------------
// Host driver
// ---------------------------------------------------------------------------
extern "C" void kernel_launch(void* const* d_in, const int* in_sizes, int n_in,
                              void* d_out, int out_size)
{
    const float* x   = (const float*)d_in[0];
    const float* wq  = (const float*)d_in[1];
    const float* bq  = (const float*)d_in[2];
    const float* wk  = (const float*)d_in[3];
    const float* bk  = (const float*)d_in[4];
    const float* wv  = (const float*)d_in[5];
    const float* bv  = (const float*)d_in[6];
    const float* wo  = (const float*)d_in[7];
    const float* bo  = (const float*)d_in[8];
    const float* g1  = (const float*)d_in[9];
    const float* be1 = (const float*)d_in[10];
    const float* w1  = (const float*)d_in[11];
    const float* b1  = (const float*)d_in[12];
    const float* w2  = (const float*)d_in[13];
    const float* b2  = (const float*)d_in[14];
    const float* g2  = (const float*)d_in[15];
    const float* be2 = (const float*)d_in[16];

    float *gx, *gtmp;
    __half *gxh, *gqkv, *gattn, *gffn, *gwH;
    cudaGetSymbolAddress((void**)&gx,    g_x);
    cudaGetSymbolAddress((void**)&gxh,   g_xh);
    cudaGetSymbolAddress((void**)&gqkv,  g_qkv);
    cudaGetSymbolAddress((void**)&gattn, g_attn);
    cudaGetSymbolAddress((void**)&gtmp,  g_tmp);
    cudaGetSymbolAddress((void**)&gffn,  g_ffn);
    cudaGetSymbolAddress((void**)&gwH,   g_wH);

    constexpr int SM_H = smem_bytes<128, 128>();   // 61440
    (void)cudaFuncSetAttribute(mma_gemm<128,128,M_QKV>,  cudaFuncAttributeMaxDynamicSharedMemorySize, SM_H);
    (void)cudaFuncSetAttribute(mma_gemm<128,128,M_RES>,  cudaFuncAttributeMaxDynamicSharedMemorySize, SM_H);
    (void)cudaFuncSetAttribute(mma_gemm<128,128,M_GELU>, cudaFuncAttributeMaxDynamicSharedMemorySize, SM_H);
    (void)cudaFuncSetAttribute(flash_k, cudaFuncAttributeMaxDynamicSharedMemorySize, FA_SMEM);

    copy_half<<<512, 256>>>(x, gx, gxh, M_ROWS * D_ / 4);
    prep_all<<<24576, dim3(32, 8)>>>(wq, wk, wv, wo, w1, w2, gwH);

    const __half* gq  = gqkv;
    const __half* gk  = gqkv + MD;
    const __half* gvT = gqkv + 2 * MD;

    const dim3 gQKV(1536 / 128, M_ROWS / 128);   // (12, 32)
    const dim3 gOP(512 / 128, M_ROWS / 128);     // (4, 32)
    const dim3 gF1(2048 / 128, M_ROWS / 128);    // (16, 32)
    const dim3 gFA(S_ / 128, B_ * H_);           // (8, 32)

    for (int l = 0; l < L_; l++) {
        const __half* wqkvH_l = gwH + OFF_TQKV + (long)l * SZ_QKV;
        const __half* woH_l   = gwH + OFF_TO   + (long)l * SZ_O;
        const __half* w1H_l   = gwH + OFF_T1   + (long)l * SZ_1;
        const __half* w2H_l   = gwH + OFF_T2   + (long)l * SZ_2;
        const float* bq_l = bq + (long)l * D_;
        const float* bk_l = bk + (long)l * D_;
        const float* bv_l = bv + (long)l * D_;
        const float* bo_l = bo + (long)l * D_;
        const float* b1_l = b1 + (long)l * F_;
        const float* b2_l = b2 + (long)l * D_;
        const float* g1_l = g1 + (long)l * D_;
        const float* g2_l = g2 + (long)l * D_;
        const float* be1_l = be1 + (long)l * D_;
        const float* be2_l = be2 + (long)l * D_;

        // fused QKV projection -> q,k [B,H,S,DH], vT [B,H,DH,S] (half)
        mma_gemm<128,128,M_QKV><<<gQKV, 128, SM_H>>>(
            gxh, wqkvH_l, bq_l, bk_l, bv_l, nullptr, nullptr, gqkv, 1536, 512);

        // fused attention
        flash_k<<<gFA, 256, FA_SMEM>>>(gq, gk, gvT, gattn);

        // O projection + bias + residual (fp32 out)
        mma_gemm<128,128,M_RES><<<gOP, 128, SM_H>>>(
            gattn, woH_l, bo_l, nullptr, nullptr, gx, gtmp, nullptr, 512, 512);
        ln_k<<<M_ROWS, 128>>>(gtmp, g1_l, be1_l, gx, gxh);

        // FFN1 + GELU (half out)
        mma_gemm<128,128,M_GELU><<<gF1, 128, SM_H>>>(
            gxh, w1H_l, b1_l, nullptr, nullptr, nullptr, nullptr, gffn, 2048, 512);
        // FFN2 + bias + residual (fp32 out)
        mma_gemm<128,128,M_RES><<<gOP, 128, SM_H>>>(
            gffn, w2H_l, b2_l, nullptr, nullptr, gx, gtmp, nullptr, 512, 2048);
        ln_k<<<M_ROWS, 128>>>(gtmp, g2_l, be2_l,
                              (l == L_ - 1) ? (float*)d_out : gx, gxh);
    }
}

// round 8
// speedup vs baseline: 6.6328x; 1.0374x over previous
#include <cuda_runtime.h>
#include <cuda_fp16.h>
#include <math.h>
#include <stdint.h>

// Problem constants
static constexpr int B_ = 4, S_ = 1024, D_ = 512, H_ = 8, F_ = 2048, DH_ = 64, L_ = 8;
static constexpr int M_ROWS = B_ * S_;           // 4096
static constexpr float QK_SCALE = 0.125f;        // 1/sqrt(64)
static constexpr float LN_EPS = 1e-5f;

static constexpr long MD = (long)M_ROWS * D_;    // 2097152
// transposed half weight slabs: [N,K] row-major per layer
static constexpr long SZ_QKV = 1536L * 512, SZ_O = 512L * 512, SZ_1 = 2048L * 512, SZ_2 = 512L * 2048;
static constexpr long OFF_TQKV = 0, OFF_TO = 8 * SZ_QKV, OFF_T1 = OFF_TO + 8 * SZ_O, OFF_T2 = OFF_T1 + 8 * SZ_1;

// Scratch (device globals; no allocation anywhere)
__device__ float g_x[M_ROWS * D_];                          // exact fp32 residual stream
__device__ __align__(16) __half g_xh[M_ROWS * D_];          // half copy for GEMM A
__device__ __align__(16) __half g_qkv[3 * M_ROWS * D_];     // q,k [B,H,S,DH]; vT [B,H,DH,S]
__device__ __align__(16) __half g_attn[M_ROWS * D_];
__device__ float g_tmp[M_ROWS * D_];
__device__ __align__(16) __half g_ffn[M_ROWS * F_];
__device__ __align__(16) __half g_wH[8 * (SZ_QKV + SZ_O + SZ_1 + SZ_2)];   // ~50 MB

enum { M_RES = 2, M_GELU = 3, M_QKV = 6 };

// ---------------------------------------------------------------------------
// helpers
// ---------------------------------------------------------------------------
__device__ __forceinline__ void cpa16(uint32_t smem, const void* gptr) {
    asm volatile("cp.async.cg.shared.global [%0], [%1], 16;\n" :: "r"(smem), "l"(gptr));
}
__device__ __forceinline__ void cp_commit() {
    asm volatile("cp.async.commit_group;\n" ::);
}
template <int N>
__device__ __forceinline__ void cp_wait() {
    asm volatile("cp.async.wait_group %0;\n" :: "n"(N));
}
__device__ __forceinline__ uint32_t smem_u32(const void* p) {
    return (uint32_t)__cvta_generic_to_shared(p);
}

// ldmatrix x4: 4 8x8 fp16 matrices; lane i supplies row address of matrix i/8.
__device__ __forceinline__ void ldsm4(uint32_t& r0, uint32_t& r1, uint32_t& r2,
                                      uint32_t& r3, uint32_t addr) {
    asm volatile("ldmatrix.sync.aligned.m8n8.x4.shared.b16 {%0,%1,%2,%3}, [%4];"
                 : "=r"(r0), "=r"(r1), "=r"(r2), "=r"(r3) : "r"(addr));
}

// m16n8k16 f16 mma, fp32 accumulate
__device__ __forceinline__ void mma16(float* c, const uint32_t* a, const uint32_t* b) {
    asm("mma.sync.aligned.m16n8k16.row.col.f32.f16.f16.f32 "
        "{%0,%1,%2,%3}, {%4,%5,%6,%7}, {%8,%9}, {%0,%1,%2,%3};"
        : "+f"(c[0]), "+f"(c[1]), "+f"(c[2]), "+f"(c[3])
        : "r"(a[0]), "r"(a[1]), "r"(a[2]), "r"(a[3]), "r"(b[0]), "r"(b[1]));
}

// ---------------------------------------------------------------------------
// fp16 mma GEMM: 128 threads, 4 warps of 64x(BN/2), BK=32, 3-stage cp.async.
// C[m,n] = A[m,k] (half, row-major) * Bt[n,k] (half, row-major)^T
// Fragments loaded via ldmatrix.x4.
// ---------------------------------------------------------------------------
static constexpr int G_ASTR = 40;  // halfs per row (32 + 8 pad)
template <int BM, int BN>
static constexpr int smem_bytes() { return 3 * (BM + BN) * G_ASTR * 2; }

template <int BM, int BN, int MODE>
__global__ __launch_bounds__(128)
void mma_gemm(const __half* __restrict__ A, const __half* __restrict__ Bm,
              const float* __restrict__ b0, const float* __restrict__ b1,
              const float* __restrict__ b2, const float* __restrict__ res,
              float* __restrict__ Cf, __half* __restrict__ Ch, int N, int K)
{
    constexpr int BK = 32;
    constexpr int WM = 64, WN = BN / 2;
    constexpr int MI = WM / 16, NI = WN / 8;     // 4, (8|4)
    constexpr int ASZ = BM * G_ASTR;             // halfs per A stage
    constexpr int BSZ = BN * G_ASTR;

    extern __shared__ __align__(16) __half smh[];
    __half* As = smh;
    __half* Bs = smh + 3 * ASZ;

    const int bm = blockIdx.y * BM;
    const int bn = blockIdx.x * BN;
    const int tid = threadIdx.x;
    const int lane = tid & 31;
    const int warp = tid >> 5;
    const int wm0 = (warp >> 1) * WM;
    const int wn0 = (warp & 1) * WN;
    const int lr = lane >> 2;
    const int lc = lane & 3;
    // ldmatrix address components
    const int arow = lane & 15, acol = (lane >> 4) << 3;            // A/x4 map
    const int brow = ((lane >> 4) << 3) + (lane & 7);               // B/x4 map
    const int bcol = ((lane >> 3) & 1) << 3;

    float acc[MI][NI][4];
    #pragma unroll
    for (int i = 0; i < MI; i++)
        #pragma unroll
        for (int j = 0; j < NI; j++)
            #pragma unroll
            for (int q = 0; q < 4; q++) acc[i][j][q] = 0.0f;

    auto load_stage = [&](int j) {
        const int st = j % 3;
        __half* as = As + st * ASZ;
        #pragma unroll
        for (int c = tid; c < BM * 4; c += 128) {
            int r = c >> 2, q = (c & 3) * 8;
            cpa16(smem_u32(as + r * G_ASTR + q), A + (long)(bm + r) * K + j * BK + q);
        }
        __half* bs = Bs + st * BSZ;
        #pragma unroll
        for (int c = tid; c < BN * 4; c += 128) {
            int r = c >> 2, q = (c & 3) * 8;
            cpa16(smem_u32(bs + r * G_ASTR + q), Bm + (long)(bn + r) * K + j * BK + q);
        }
        cp_commit();
    };

    const int NIT = K / BK;
    load_stage(0);
    if (NIT > 1) load_stage(1);

    for (int it = 0; it < NIT; it++) {
        if (it + 2 < NIT) { load_stage(it + 2); cp_wait<2>(); }
        else if (it + 2 == NIT) { cp_wait<1>(); }
        else { cp_wait<0>(); }
        __syncthreads();

        const int st = it % 3;
        const __half* as = As + st * ASZ;
        const __half* bs = Bs + st * BSZ;
        #pragma unroll
        for (int kk = 0; kk < BK; kk += 16) {
            uint32_t af[MI][4];
            #pragma unroll
            for (int mi = 0; mi < MI; mi++)
                ldsm4(af[mi][0], af[mi][1], af[mi][2], af[mi][3],
                      smem_u32(as + (wm0 + mi * 16 + arow) * G_ASTR + kk + acol));
            uint32_t bf[NI][2];
            #pragma unroll
            for (int ni = 0; ni < NI; ni += 2)
                ldsm4(bf[ni][0], bf[ni][1], bf[ni + 1][0], bf[ni + 1][1],
                      smem_u32(bs + (wn0 + ni * 8 + brow) * G_ASTR + kk + bcol));
            #pragma unroll
            for (int mi = 0; mi < MI; mi++)
                #pragma unroll
                for (int ni = 0; ni < NI; ni++)
                    mma16(acc[mi][ni], af[mi], bf[ni]);
        }
        __syncthreads();
    }

    // Epilogue (C frag: c0,c1=(lr, 2lc,2lc+1), c2,c3=(lr+8,...))
    #pragma unroll
    for (int mi = 0; mi < MI; mi++) {
        #pragma unroll
        for (int ni = 0; ni < NI; ni++) {
            #pragma unroll
            for (int ri = 0; ri < 2; ri++) {
                const int m = bm + wm0 + mi * 16 + lr + ri * 8;
                const int n = bn + wn0 + ni * 8 + lc * 2;
                float v0 = acc[mi][ni][ri * 2 + 0];
                float v1 = acc[mi][ni][ri * 2 + 1];
                if (MODE == M_RES) {
                    long o = (long)m * N + n;
                    Cf[o]     = v0 + b0[n]     + res[o];
                    Cf[o + 1] = v1 + b0[n + 1] + res[o + 1];
                } else if (MODE == M_GELU) {
                    v0 += b0[n]; v1 += b0[n + 1];
                    float g0 = 0.5f * v0 * (1.0f + erff(v0 * 0.70710678118654752f));
                    float g1 = 0.5f * v1 * (1.0f + erff(v1 * 0.70710678118654752f));
                    *reinterpret_cast<__half2*>(Ch + (long)m * N + n) = __floats2half2_rn(g0, g1);
                } else { // M_QKV: n in [0,1536): q,k -> [B,H,S,DH]; v -> [B,H,DH,S]
                    const int t = n >> 9;
                    const int colD = n & 511;
                    const float* bb = (t == 0) ? b0 : ((t == 1) ? b1 : b2);
                    const int b = m >> 10, s = m & 1023, h = colD >> 6, dh0 = colD & 63;
                    const int bh = (b << 3) + h;
                    float u0 = v0 + bb[colD], u1 = v1 + bb[colD + 1];
                    if (t == 0) { u0 *= QK_SCALE; u1 *= QK_SCALE; }
                    if (t == 2) {
                        long o = 2 * MD + ((long)bh << 16) + ((long)dh0 << 10) + s;
                        Ch[o]        = __float2half_rn(u0);
                        Ch[o + 1024] = __float2half_rn(u1);
                    } else {
                        long o = (long)t * MD + (((long)bh * S_ + s) << 6) + dh0;
                        *reinterpret_cast<__half2*>(Ch + o) = __floats2half2_rn(u0, u1);
                    }
                }
            }
        }
    }
}

// ---------------------------------------------------------------------------
// Flash attention (fp16, ldmatrix): one CTA per (q-tile 128, b*h). 8 warps.
// Q,K: [B,H,S,DH] half (Q pre-scaled). Vt: [B,H,DH,S] half. Online softmax.
// ---------------------------------------------------------------------------
static constexpr int FA_KSTR = 72;                    // halfs (64 + 8 pad)
static constexpr int FA_VSTR = 136;                   // halfs (128 + 8 pad)
static constexpr int FA_KSZ = 128 * FA_KSTR;          // 9216 halfs
static constexpr int FA_VSZ = 64 * FA_VSTR;           // 8704 halfs
static constexpr int FA_STAGE = FA_KSZ + FA_VSZ;      // 17920 halfs
static constexpr int FA_PSTR = 136;
static constexpr int FA_PWARP = 16 * FA_PSTR;         // 2176 halfs
static constexpr int FA_SMEM = (2 * FA_STAGE + 8 * FA_PWARP) * 2;  // 106496 B

__global__ __launch_bounds__(256)
void flash_k(const __half* __restrict__ Q, const __half* __restrict__ Kt,
             const __half* __restrict__ Vt, __half* __restrict__ O)
{
    extern __shared__ __align__(16) __half smh[];
    __half* kv = smh;
    __half* pb = smh + 2 * FA_STAGE;

    const int bh = blockIdx.y;
    const int qt = blockIdx.x;
    const int tid = threadIdx.x, lane = tid & 31, w = tid >> 5;
    const int lr = lane >> 2, lc = lane & 3;
    const int arow = lane & 15, acol = (lane >> 4) << 3;
    const int brow = ((lane >> 4) << 3) + (lane & 7);
    const int bcol = ((lane >> 3) & 1) << 3;
    const long base = (long)bh * S_ * DH_;

    auto loadkv = [&](int j) {
        __half* ks = kv + (j & 1) * FA_STAGE;
        __half* vs = ks + FA_KSZ;
        const __half* kg = Kt + base + (long)j * 128 * 64;   // rows of [s][dh]
        const __half* vg = Vt + base + (long)j * 128;        // col-slice of [dh][s=1024]
        #pragma unroll
        for (int c = tid; c < 1024; c += 256) {              // K: 128 rows x 8 chunks
            int r = c >> 3, q = (c & 7) * 8;
            cpa16(smem_u32(ks + r * FA_KSTR + q), kg + r * 64 + q);
        }
        #pragma unroll
        for (int c = tid; c < 1024; c += 256) {              // V: 64 rows x 16 chunks
            int r = c >> 4, q = (c & 15) * 8;
            cpa16(smem_u32(vs + r * FA_VSTR + q), vg + (long)r * 1024 + q);
        }
        cp_commit();
    };

    loadkv(0);

    // Stage Q tile into P region (128 x 64 halfs, stride FA_KSTR), grab fragments.
    {
        const __half* qg = Q + base + (long)qt * 128 * 64;
        #pragma unroll
        for (int c = tid; c < 1024; c += 256) {
            int r = c >> 3, q = (c & 7) * 8;
            *reinterpret_cast<uint4*>(pb + r * FA_KSTR + q) =
                *reinterpret_cast<const uint4*>(qg + r * 64 + q);
        }
    }
    __syncthreads();
    uint32_t qf[4][4];
    #pragma unroll
    for (int kk = 0; kk < 4; kk++)
        ldsm4(qf[kk][0], qf[kk][1], qf[kk][2], qf[kk][3],
              smem_u32(pb + (w * 16 + arow) * FA_KSTR + kk * 16 + acol));

    float m0 = -1e30f, m1 = -1e30f, l0 = 0.0f, l1 = 0.0f;
    float oacc[8][4] = {};
    __half* pw = pb + w * FA_PWARP;

    for (int j = 0; j < 8; j++) {
        if (j + 1 < 8) { loadkv(j + 1); cp_wait<1>(); }
        else           { cp_wait<0>(); }
        __syncthreads();   // stage j ready; also protects P region reuse

        const __half* ks = kv + (j & 1) * FA_STAGE;
        const __half* vs = ks + FA_KSZ;

        // S = Q K^T (16 q-rows x 128 s-cols per warp); K smem [s][dh] = B [n][k]
        float sacc[16][4];
        #pragma unroll
        for (int ni = 0; ni < 16; ni++)
            #pragma unroll
            for (int q = 0; q < 4; q++) sacc[ni][q] = 0.0f;
        #pragma unroll
        for (int kk = 0; kk < 4; kk++) {
            #pragma unroll
            for (int ni = 0; ni < 16; ni += 2) {
                uint32_t b00, b01, b10, b11;
                ldsm4(b00, b01, b10, b11,
                      smem_u32(ks + (ni * 8 + brow) * FA_KSTR + kk * 16 + bcol));
                uint32_t bf0[2] = {b00, b01}, bf1[2] = {b10, b11};
                mma16(sacc[ni], qf[kk], bf0);
                mma16(sacc[ni + 1], qf[kk], bf1);
            }
        }

        // online softmax
        float mx0 = -1e30f, mx1 = -1e30f;
        #pragma unroll
        for (int ni = 0; ni < 16; ni++) {
            mx0 = fmaxf(mx0, fmaxf(sacc[ni][0], sacc[ni][1]));
            mx1 = fmaxf(mx1, fmaxf(sacc[ni][2], sacc[ni][3]));
        }
        mx0 = fmaxf(mx0, __shfl_xor_sync(0xFFFFFFFFu, mx0, 1));
        mx0 = fmaxf(mx0, __shfl_xor_sync(0xFFFFFFFFu, mx0, 2));
        mx1 = fmaxf(mx1, __shfl_xor_sync(0xFFFFFFFFu, mx1, 1));
        mx1 = fmaxf(mx1, __shfl_xor_sync(0xFFFFFFFFu, mx1, 2));
        const float mn0 = fmaxf(m0, mx0), mn1 = fmaxf(m1, mx1);
        const float al0 = expf(m0 - mn0), al1 = expf(m1 - mn1);

        float rs0 = 0.0f, rs1 = 0.0f;
        #pragma unroll
        for (int ni = 0; ni < 16; ni++) {
            float p0 = expf(sacc[ni][0] - mn0);
            float p1 = expf(sacc[ni][1] - mn0);
            float p2 = expf(sacc[ni][2] - mn1);
            float p3 = expf(sacc[ni][3] - mn1);
            rs0 += p0 + p1; rs1 += p2 + p3;
            const int col = ni * 8 + 2 * lc;
            *reinterpret_cast<__half2*>(pw + lr * FA_PSTR + col)       = __floats2half2_rn(p0, p1);
            *reinterpret_cast<__half2*>(pw + (lr + 8) * FA_PSTR + col) = __floats2half2_rn(p2, p3);
        }
        rs0 += __shfl_xor_sync(0xFFFFFFFFu, rs0, 1);
        rs0 += __shfl_xor_sync(0xFFFFFFFFu, rs0, 2);
        rs1 += __shfl_xor_sync(0xFFFFFFFFu, rs1, 1);
        rs1 += __shfl_xor_sync(0xFFFFFFFFu, rs1, 2);
        m0 = mn0; m1 = mn1;
        l0 = l0 * al0 + rs0;
        l1 = l1 * al1 + rs1;
        #pragma unroll
        for (int ni = 0; ni < 8; ni++) {
            oacc[ni][0] *= al0; oacc[ni][1] *= al0;
            oacc[ni][2] *= al1; oacc[ni][3] *= al1;
        }
        __syncwarp();

        // O += P V : P (16 x 128) A-operand from pw; Vt smem [dh][s] = B [n][k]
        #pragma unroll
        for (int kk2 = 0; kk2 < 8; kk2++) {
            uint32_t af[4];
            ldsm4(af[0], af[1], af[2], af[3],
                  smem_u32(pw + arow * FA_PSTR + kk2 * 16 + acol));
            #pragma unroll
            for (int ni = 0; ni < 8; ni += 2) {
                uint32_t b00, b01, b10, b11;
                ldsm4(b00, b01, b10, b11,
                      smem_u32(vs + (ni * 8 + brow) * FA_VSTR + kk2 * 16 + bcol));
                uint32_t bf0[2] = {b00, b01}, bf1[2] = {b10, b11};
                mma16(oacc[ni], af, bf0);
                mma16(oacc[ni + 1], af, bf1);
            }
        }
        __syncthreads();  // before next loadkv overwrites a stage
    }

    // epilogue: divide by l, write [B,S,D] half
    const float inv0 = 1.0f / l0, inv1 = 1.0f / l1;
    const int b = bh >> 3, h = bh & 7;
    const int r0 = qt * 128 + w * 16 + lr;
    #pragma unroll
    for (int ni = 0; ni < 8; ni++) {
        const int n = h * 64 + ni * 8 + 2 * lc;
        long o0 = ((long)(b * S_ + r0)) * D_ + n;
        long o1 = ((long)(b * S_ + r0 + 8)) * D_ + n;
        *reinterpret_cast<__half2*>(O + o0) = __floats2half2_rn(oacc[ni][0] * inv0, oacc[ni][1] * inv0);
        *reinterpret_cast<__half2*>(O + o1) = __floats2half2_rn(oacc[ni][2] * inv1, oacc[ni][3] * inv1);
    }
}

// ---------------------------------------------------------------------------
// Merged weight prep: transpose + fp16 convert all six weights in one launch.
// out_half[n*K + k] = (half) in_f32[k*N + n]
// ---------------------------------------------------------------------------
__global__ __launch_bounds__(256) void prep_all(
    const float* __restrict__ wq, const float* __restrict__ wk,
    const float* __restrict__ wv, const float* __restrict__ wo,
    const float* __restrict__ w1, const float* __restrict__ w2,
    __half* __restrict__ out)
{
    __shared__ float t[32][33];
    const int id = blockIdx.x;
    const float* src; __half* dst; int K, N, ki, ni;
    if (id < 8192) {                    // wq/wk/wv/wo: 4 x 8 layers x 256 tiles
        const int wsel = id >> 11, rem = id & 2047;
        const int layer = rem >> 8, tile = rem & 255;
        K = 512; N = 512; ki = tile >> 4; ni = tile & 15;
        src = (wsel == 0 ? wq : wsel == 1 ? wk : wsel == 2 ? wv : wo) + (long)layer * 262144;
        dst = out + (wsel < 3 ? OFF_TQKV + (long)layer * SZ_QKV + (long)wsel * 262144
                              : OFF_TO + (long)layer * SZ_O);
    } else if (id < 16384) {            // w1: 8 layers x 1024 tiles
        const int rem = id - 8192, layer = rem >> 10, tile = rem & 1023;
        K = 512; N = 2048; ki = tile >> 6; ni = tile & 63;
        src = w1 + (long)layer * 1048576;
        dst = out + OFF_T1 + (long)layer * SZ_1;
    } else {                            // w2: 8 layers x 1024 tiles
        const int rem = id - 16384, layer = rem >> 10, tile = rem & 1023;
        K = 2048; N = 512; ki = tile >> 4; ni = tile & 15;
        src = w2 + (long)layer * 1048576;
        dst = out + OFF_T2 + (long)layer * SZ_2;
    }
    const int k0 = ki * 32, n0 = ni * 32;
    #pragma unroll
    for (int i = threadIdx.y; i < 32; i += 8)
        t[i][threadIdx.x] = src[(long)(k0 + i) * N + n0 + threadIdx.x];
    __syncthreads();
    #pragma unroll
    for (int i = threadIdx.y; i < 32; i += 8)
        dst[(long)(n0 + i) * K + k0 + threadIdx.x] = __float2half_rn(t[threadIdx.x][i]);
}

// copy x -> gx (fp32) and gxh (half)
__global__ __launch_bounds__(256) void copy_half(const float* __restrict__ x,
                                                 float* __restrict__ gx,
                                                 __half* __restrict__ gxh, int n4)
{
    int i = blockIdx.x * blockDim.x + threadIdx.x;
    int stride = gridDim.x * blockDim.x;
    for (; i < n4; i += stride) {
        float4 v = reinterpret_cast<const float4*>(x)[i];
        reinterpret_cast<float4*>(gx)[i] = v;
        reinterpret_cast<__half2*>(gxh)[2 * i]     = __floats2half2_rn(v.x, v.y);
        reinterpret_cast<__half2*>(gxh)[2 * i + 1] = __floats2half2_rn(v.z, v.w);
    }
}

// ---------------------------------------------------------------------------
// Row LayerNorm over 512 elements; fp32 out + half out_h.
// ---------------------------------------------------------------------------
__global__ __launch_bounds__(128) void ln_k(const float* __restrict__ in,
                                            const float* __restrict__ g,
                                            const float* __restrict__ be,
                                            float* __restrict__ out,
                                            __half* __restrict__ out_h)
{
    const int row = blockIdx.x;
    const int t = threadIdx.x;
    const float4 v = reinterpret_cast<const float4*>(in + (long)row * D_)[t];

    float s  = v.x + v.y + v.z + v.w;
    float sq = v.x * v.x + v.y * v.y + v.z * v.z + v.w * v.w;
    #pragma unroll
    for (int o = 16; o; o >>= 1) {
        s  += __shfl_xor_sync(0xFFFFFFFFu, s, o);
        sq += __shfl_xor_sync(0xFFFFFFFFu, sq, o);
    }
    __shared__ float sh0[4], sh1[4];
    if ((t & 31) == 0) { sh0[t >> 5] = s; sh1[t >> 5] = sq; }
    __syncthreads();
    s  = sh0[0] + sh0[1] + sh0[2] + sh0[3];
    sq = sh1[0] + sh1[1] + sh1[2] + sh1[3];

    const float mean = s * (1.0f / D_);
    const float var  = sq * (1.0f / D_) - mean * mean;
    const float inv  = rsqrtf(var + LN_EPS);

    const float4 gg = reinterpret_cast<const float4*>(g)[t];
    const float4 bb = reinterpret_cast<const float4*>(be)[t];
    float4 o4;
    o4.x = (v.x - mean) * inv * gg.x + bb.x;
    o4.y = (v.y - mean) * inv * gg.y + bb.y;
    o4.z = (v.z - mean) * inv * gg.z + bb.z;
    o4.w = (v.w - mean) * inv * gg.w + bb.w;
    reinterpret_cast<float4*>(out + (long)row * D_)[t] = o4;
    __half2* oh = reinterpret_cast<__half2*>(out_h + (long)row * D_);
    oh[2 * t]     = __floats2half2_rn(o4.x, o4.y);
    oh[2 * t + 1] = __floats2half2_rn(o4.z, o4.w);
}

// ---------------------------------------------------------------------------
// Host driver
// ---------------------------------------------------------------------------
extern "C" void kernel_launch(void* const* d_in, const int* in_sizes, int n_in,
                              void* d_out, int out_size)
{
    const float* x   = (const float*)d_in[0];
    const float* wq  = (const float*)d_in[1];
    const float* bq  = (const float*)d_in[2];
    const float* wk  = (const float*)d_in[3];
    const float* bk  = (const float*)d_in[4];
    const float* wv  = (const float*)d_in[5];
    const float* bv  = (const float*)d_in[6];
    const float* wo  = (const float*)d_in[7];
    const float* bo  = (const float*)d_in[8];
    const float* g1  = (const float*)d_in[9];
    const float* be1 = (const float*)d_in[10];
    const float* w1  = (const float*)d_in[11];
    const float* b1  = (const float*)d_in[12];
    const float* w2  = (const float*)d_in[13];
    const float* b2  = (const float*)d_in[14];
    const float* g2  = (const float*)d_in[15];
    const float* be2 = (const float*)d_in[16];

    float *gx, *gtmp;
    __half *gxh, *gqkv, *gattn, *gffn, *gwH;
    cudaGetSymbolAddress((void**)&gx,    g_x);
    cudaGetSymbolAddress((void**)&gxh,   g_xh);
    cudaGetSymbolAddress((void**)&gqkv,  g_qkv);
    cudaGetSymbolAddress((void**)&gattn, g_attn);
    cudaGetSymbolAddress((void**)&gtmp,  g_tmp);
    cudaGetSymbolAddress((void**)&gffn,  g_ffn);
    cudaGetSymbolAddress((void**)&gwH,   g_wH);

    constexpr int SM_H = smem_bytes<128, 128>();   // 61440
    (void)cudaFuncSetAttribute(mma_gemm<128,128,M_QKV>,  cudaFuncAttributeMaxDynamicSharedMemorySize, SM_H);
    (void)cudaFuncSetAttribute(mma_gemm<128,128,M_RES>,  cudaFuncAttributeMaxDynamicSharedMemorySize, SM_H);
    (void)cudaFuncSetAttribute(mma_gemm<128,128,M_GELU>, cudaFuncAttributeMaxDynamicSharedMemorySize, SM_H);
    (void)cudaFuncSetAttribute(flash_k, cudaFuncAttributeMaxDynamicSharedMemorySize, FA_SMEM);

    copy_half<<<512, 256>>>(x, gx, gxh, M_ROWS * D_ / 4);
    prep_all<<<24576, dim3(32, 8)>>>(wq, wk, wv, wo, w1, w2, gwH);

    const __half* gq  = gqkv;
    const __half* gk  = gqkv + MD;
    const __half* gvT = gqkv + 2 * MD;

    const dim3 gQKV(1536 / 128, M_ROWS / 128);   // (12, 32)
    const dim3 gOP(512 / 128, M_ROWS / 128);     // (4, 32)
    const dim3 gF1(2048 / 128, M_ROWS / 128);    // (16, 32)
    const dim3 gFA(S_ / 128, B_ * H_);           // (8, 32)

    for (int l = 0; l < L_; l++) {
        const __half* wqkvH_l = gwH + OFF_TQKV + (long)l * SZ_QKV;
        const __half* woH_l   = gwH + OFF_TO   + (long)l * SZ_O;
        const __half* w1H_l   = gwH + OFF_T1   + (long)l * SZ_1;
        const __half* w2H_l   = gwH + OFF_T2   + (long)l * SZ_2;
        const float* bq_l = bq + (long)l * D_;
        const float* bk_l = bk + (long)l * D_;
        const float* bv_l = bv + (long)l * D_;
        const float* bo_l = bo + (long)l * D_;
        const float* b1_l = b1 + (long)l * F_;
        const float* b2_l = b2 + (long)l * D_;
        const float* g1_l = g1 + (long)l * D_;
        const float* g2_l = g2 + (long)l * D_;
        const float* be1_l = be1 + (long)l * D_;
        const float* be2_l = be2 + (long)l * D_;

        // fused QKV projection -> q,k [B,H,S,DH], vT [B,H,DH,S] (half)
        mma_gemm<128,128,M_QKV><<<gQKV, 128, SM_H>>>(
            gxh, wqkvH_l, bq_l, bk_l, bv_l, nullptr, nullptr, gqkv, 1536, 512);

        // fused attention
        flash_k<<<gFA, 256, FA_SMEM>>>(gq, gk, gvT, gattn);

        // O projection + bias + residual (fp32 out)
        mma_gemm<128,128,M_RES><<<gOP, 128, SM_H>>>(
            gattn, woH_l, bo_l, nullptr, nullptr, gx, gtmp, nullptr, 512, 512);
        ln_k<<<M_ROWS, 128>>>(gtmp, g1_l, be1_l, gx, gxh);

        // FFN1 + GELU (half out)
        mma_gemm<128,128,M_GELU><<<gF1, 128, SM_H>>>(
            gxh, w1H_l, b1_l, nullptr, nullptr, nullptr, nullptr, gffn, 2048, 512);
        // FFN2 + bias + residual (fp32 out)
        mma_gemm<128,128,M_RES><<<gOP, 128, SM_H>>>(
            gffn, w2H_l, b2_l, nullptr, nullptr, gx, gtmp, nullptr, 512, 2048);
        ln_k<<<M_ROWS, 128>>>(gtmp, g2_l, be2_l,
                              (l == L_ - 1) ? (float*)d_out : gx, gxh);
    }
}

// round 9
// speedup vs baseline: 6.9313x; 1.0450x over previous
#include <cuda_runtime.h>
#include <cuda_fp16.h>
#include <math.h>
#include <stdint.h>

// Problem constants
static constexpr int B_ = 4, S_ = 1024, D_ = 512, H_ = 8, F_ = 2048, DH_ = 64, L_ = 8;
static constexpr int M_ROWS = B_ * S_;           // 4096
static constexpr float QK_SCALE = 0.125f;        // 1/sqrt(64)
static constexpr float LN_EPS = 1e-5f;

static constexpr long MD = (long)M_ROWS * D_;    // 2097152
// transposed half weight slabs: [N,K] row-major per layer
static constexpr long SZ_QKV = 1536L * 512, SZ_O = 512L * 512, SZ_1 = 2048L * 512, SZ_2 = 512L * 2048;
static constexpr long OFF_TQKV = 0, OFF_TO = 8 * SZ_QKV, OFF_T1 = OFF_TO + 8 * SZ_O, OFF_T2 = OFF_T1 + 8 * SZ_1;

// Scratch (device globals; no allocation anywhere)
__device__ float g_x[M_ROWS * D_];                          // exact fp32 residual stream
__device__ __align__(16) __half g_xh[M_ROWS * D_];          // half copy for GEMM A
__device__ __align__(16) __half g_qkv[3 * M_ROWS * D_];     // q,k [B,H,S,DH]; vT [B,H,DH,S]
__device__ __align__(16) __half g_attn[M_ROWS * D_];
__device__ float g_tmp[M_ROWS * D_];
__device__ __align__(16) __half g_ffn[M_ROWS * F_];
__device__ __align__(16) __half g_wH[8 * (SZ_QKV + SZ_O + SZ_1 + SZ_2)];   // ~50 MB

enum { M_RES = 2, M_GELU = 3, M_QKV = 6 };

// ---------------------------------------------------------------------------
// helpers
// ---------------------------------------------------------------------------
__device__ __forceinline__ void cpa16(uint32_t smem, const void* gptr) {
    asm volatile("cp.async.cg.shared.global [%0], [%1], 16;\n" :: "r"(smem), "l"(gptr));
}
__device__ __forceinline__ void cp_commit() {
    asm volatile("cp.async.commit_group;\n" ::);
}
template <int N>
__device__ __forceinline__ void cp_wait() {
    asm volatile("cp.async.wait_group %0;\n" :: "n"(N));
}
__device__ __forceinline__ uint32_t smem_u32(const void* p) {
    return (uint32_t)__cvta_generic_to_shared(p);
}

__device__ __forceinline__ void ldsm4(uint32_t& r0, uint32_t& r1, uint32_t& r2,
                                      uint32_t& r3, uint32_t addr) {
    asm volatile("ldmatrix.sync.aligned.m8n8.x4.shared.b16 {%0,%1,%2,%3}, [%4];"
                 : "=r"(r0), "=r"(r1), "=r"(r2), "=r"(r3) : "r"(addr));
}

// m16n8k16 f16 mma, fp32 accumulate
__device__ __forceinline__ void mma16(float* c, const uint32_t* a, const uint32_t* b) {
    asm("mma.sync.aligned.m16n8k16.row.col.f32.f16.f16.f32 "
        "{%0,%1,%2,%3}, {%4,%5,%6,%7}, {%8,%9}, {%0,%1,%2,%3};"
        : "+f"(c[0]), "+f"(c[1]), "+f"(c[2]), "+f"(c[3])
        : "r"(a[0]), "r"(a[1]), "r"(a[2]), "r"(a[3]), "r"(b[0]), "r"(b[1]));
}

// ---------------------------------------------------------------------------
// fp16 mma GEMM: 128 threads, 4 warps of 64x(BN/2), BK=32, 3-stage cp.async.
// C[m,n] = A[m,k] (half, row-major) * Bt[n,k] (half, row-major)^T
// ---------------------------------------------------------------------------
static constexpr int G_ASTR = 40;  // halfs per row (32 + 8 pad)
template <int BM, int BN>
static constexpr int smem_bytes() { return 3 * (BM + BN) * G_ASTR * 2; }

template <int BM, int BN, int MODE>
__global__ __launch_bounds__(128)
void mma_gemm(const __half* __restrict__ A, const __half* __restrict__ Bm,
              const float* __restrict__ b0, const float* __restrict__ b1,
              const float* __restrict__ b2, const float* __restrict__ res,
              float* __restrict__ Cf, __half* __restrict__ Ch, int N, int K)
{
    constexpr int BK = 32;
    constexpr int WM = 64, WN = BN / 2;
    constexpr int MI = WM / 16, NI = WN / 8;     // 4, (8|4)
    constexpr int ASZ = BM * G_ASTR;
    constexpr int BSZ = BN * G_ASTR;

    extern __shared__ __align__(16) __half smh[];
    __half* As = smh;
    __half* Bs = smh + 3 * ASZ;

    const int bm = blockIdx.y * BM;
    const int bn = blockIdx.x * BN;
    const int tid = threadIdx.x;
    const int lane = tid & 31;
    const int warp = tid >> 5;
    const int wm0 = (warp >> 1) * WM;
    const int wn0 = (warp & 1) * WN;
    const int lr = lane >> 2;
    const int lc = lane & 3;
    const int arow = lane & 15, acol = (lane >> 4) << 3;
    const int brow = ((lane >> 4) << 3) + (lane & 7);
    const int bcol = ((lane >> 3) & 1) << 3;

    float acc[MI][NI][4];
    #pragma unroll
    for (int i = 0; i < MI; i++)
        #pragma unroll
        for (int j = 0; j < NI; j++)
            #pragma unroll
            for (int q = 0; q < 4; q++) acc[i][j][q] = 0.0f;

    auto load_stage = [&](int j) {
        const int st = j % 3;
        __half* as = As + st * ASZ;
        #pragma unroll
        for (int c = tid; c < BM * 4; c += 128) {
            int r = c >> 2, q = (c & 3) * 8;
            cpa16(smem_u32(as + r * G_ASTR + q), A + (long)(bm + r) * K + j * BK + q);
        }
        __half* bs = Bs + st * BSZ;
        #pragma unroll
        for (int c = tid; c < BN * 4; c += 128) {
            int r = c >> 2, q = (c & 3) * 8;
            cpa16(smem_u32(bs + r * G_ASTR + q), Bm + (long)(bn + r) * K + j * BK + q);
        }
        cp_commit();
    };

    const int NIT = K / BK;
    load_stage(0);
    if (NIT > 1) load_stage(1);

    for (int it = 0; it < NIT; it++) {
        if (it + 2 < NIT) { load_stage(it + 2); cp_wait<2>(); }
        else if (it + 2 == NIT) { cp_wait<1>(); }
        else { cp_wait<0>(); }
        __syncthreads();

        const int st = it % 3;
        const __half* as = As + st * ASZ;
        const __half* bs = Bs + st * BSZ;
        #pragma unroll
        for (int kk = 0; kk < BK; kk += 16) {
            uint32_t af[MI][4];
            #pragma unroll
            for (int mi = 0; mi < MI; mi++)
                ldsm4(af[mi][0], af[mi][1], af[mi][2], af[mi][3],
                      smem_u32(as + (wm0 + mi * 16 + arow) * G_ASTR + kk + acol));
            uint32_t bf[NI][2];
            #pragma unroll
            for (int ni = 0; ni < NI; ni += 2)
                ldsm4(bf[ni][0], bf[ni][1], bf[ni + 1][0], bf[ni + 1][1],
                      smem_u32(bs + (wn0 + ni * 8 + brow) * G_ASTR + kk + bcol));
            #pragma unroll
            for (int mi = 0; mi < MI; mi++)
                #pragma unroll
                for (int ni = 0; ni < NI; ni++)
                    mma16(acc[mi][ni], af[mi], bf[ni]);
        }
        __syncthreads();
    }

    #pragma unroll
    for (int mi = 0; mi < MI; mi++) {
        #pragma unroll
        for (int ni = 0; ni < NI; ni++) {
            #pragma unroll
            for (int ri = 0; ri < 2; ri++) {
                const int m = bm + wm0 + mi * 16 + lr + ri * 8;
                const int n = bn + wn0 + ni * 8 + lc * 2;
                float v0 = acc[mi][ni][ri * 2 + 0];
                float v1 = acc[mi][ni][ri * 2 + 1];
                if (MODE == M_RES) {
                    long o = (long)m * N + n;
                    Cf[o]     = v0 + b0[n]     + res[o];
                    Cf[o + 1] = v1 + b0[n + 1] + res[o + 1];
                } else if (MODE == M_GELU) {
                    v0 += b0[n]; v1 += b0[n + 1];
                    float g0 = 0.5f * v0 * (1.0f + erff(v0 * 0.70710678118654752f));
                    float g1 = 0.5f * v1 * (1.0f + erff(v1 * 0.70710678118654752f));
                    *reinterpret_cast<__half2*>(Ch + (long)m * N + n) = __floats2half2_rn(g0, g1);
                } else { // M_QKV
                    const int t = n >> 9;
                    const int colD = n & 511;
                    const float* bb = (t == 0) ? b0 : ((t == 1) ? b1 : b2);
                    const int b = m >> 10, s = m & 1023, h = colD >> 6, dh0 = colD & 63;
                    const int bh = (b << 3) + h;
                    float u0 = v0 + bb[colD], u1 = v1 + bb[colD + 1];
                    if (t == 0) { u0 *= QK_SCALE; u1 *= QK_SCALE; }
                    if (t == 2) {
                        long o = 2 * MD + ((long)bh << 16) + ((long)dh0 << 10) + s;
                        Ch[o]        = __float2half_rn(u0);
                        Ch[o + 1024] = __float2half_rn(u1);
                    } else {
                        long o = (long)t * MD + (((long)bh * S_ + s) << 6) + dh0;
                        *reinterpret_cast<__half2*>(Ch + o) = __floats2half2_rn(u0, u1);
                    }
                }
            }
        }
    }
}

// ---------------------------------------------------------------------------
// Flash attention v3: q-tile 128 (8 warps x 16 rows), KV j-tiles of 64 rows,
// 16 iterations, double-buffered. 2 CTAs/SM (regs clamped to 128).
// Q,K: [B,H,S,DH] half (Q pre-scaled). Vt: [B,H,DH,S] half.
// ---------------------------------------------------------------------------
static constexpr int FA_STR = 72;                     // halfs (64 + 8 pad)
static constexpr int FA_KSZ = 64 * FA_STR;            // 4608 halfs per K tile
static constexpr int FA_VSZ = 64 * FA_STR;            // 4608 halfs per V tile
static constexpr int FA_STAGE = FA_KSZ + FA_VSZ;      // 9216 halfs
static constexpr int FA_PWARP = 16 * FA_STR;          // 1152 halfs per warp
static constexpr int FA_SMEM = (2 * FA_STAGE + 8 * FA_PWARP) * 2;  // 55296 B

__global__ __launch_bounds__(256, 2)
void flash_k(const __half* __restrict__ Q, const __half* __restrict__ Kt,
             const __half* __restrict__ Vt, __half* __restrict__ O)
{
    extern __shared__ __align__(16) __half smh[];
    __half* kv = smh;
    __half* pb = smh + 2 * FA_STAGE;    // P region; also Q staging (128 x 72 = 9216)

    const int bh = blockIdx.y;
    const int qt = blockIdx.x;
    const int tid = threadIdx.x, lane = tid & 31, w = tid >> 5;
    const int lr = lane >> 2, lc = lane & 3;
    const int arow = lane & 15, acol = (lane >> 4) << 3;
    const int brow = ((lane >> 4) << 3) + (lane & 7);
    const int bcol = ((lane >> 3) & 1) << 3;
    const long base = (long)bh * S_ * DH_;

    auto loadkv = [&](int j) {               // j in [0,16): 64 s-rows
        __half* ks = kv + (j & 1) * FA_STAGE;
        __half* vs = ks + FA_KSZ;
        const __half* kg = Kt + base + (long)j * 64 * 64;    // [s][dh] rows
        const __half* vg = Vt + base + (long)j * 64;         // [dh][s] col slice
        #pragma unroll
        for (int c = tid; c < 512; c += 256) {               // K: 64 rows x 8 chunks
            int r = c >> 3, q = (c & 7) * 8;
            cpa16(smem_u32(ks + r * FA_STR + q), kg + r * 64 + q);
        }
        #pragma unroll
        for (int c = tid; c < 512; c += 256) {               // V: 64 dh-rows x 8 chunks
            int r = c >> 3, q = (c & 7) * 8;
            cpa16(smem_u32(vs + r * FA_STR + q), vg + (long)r * 1024 + q);
        }
        cp_commit();
    };

    loadkv(0);

    // Stage Q tile (128 x 64 halfs, stride FA_STR) in P region; grab fragments.
    {
        const __half* qg = Q + base + (long)qt * 128 * 64;
        #pragma unroll
        for (int c = tid; c < 1024; c += 256) {
            int r = c >> 3, q = (c & 7) * 8;
            *reinterpret_cast<uint4*>(pb + r * FA_STR + q) =
                *reinterpret_cast<const uint4*>(qg + r * 64 + q);
        }
    }
    __syncthreads();
    uint32_t qf[4][4];
    #pragma unroll
    for (int kk = 0; kk < 4; kk++)
        ldsm4(qf[kk][0], qf[kk][1], qf[kk][2], qf[kk][3],
              smem_u32(pb + (w * 16 + arow) * FA_STR + kk * 16 + acol));

    float m0 = -1e30f, m1 = -1e30f, l0 = 0.0f, l1 = 0.0f;
    float oacc[8][4] = {};
    __half* pw = pb + w * FA_PWARP;

    for (int j = 0; j < 16; j++) {
        if (j + 1 < 16) { loadkv(j + 1); cp_wait<1>(); }
        else            { cp_wait<0>(); }
        __syncthreads();   // stage j ready; also protects P/Q region reuse

        const __half* ks = kv + (j & 1) * FA_STAGE;
        const __half* vs = ks + FA_KSZ;

        // S = Q K^T (16 q-rows x 64 s-cols per warp)
        float sacc[8][4];
        #pragma unroll
        for (int ni = 0; ni < 8; ni++)
            #pragma unroll
            for (int q = 0; q < 4; q++) sacc[ni][q] = 0.0f;
        #pragma unroll
        for (int kk = 0; kk < 4; kk++) {
            #pragma unroll
            for (int ni = 0; ni < 8; ni += 2) {
                uint32_t b00, b01, b10, b11;
                ldsm4(b00, b01, b10, b11,
                      smem_u32(ks + (ni * 8 + brow) * FA_STR + kk * 16 + bcol));
                uint32_t bf0[2] = {b00, b01}, bf1[2] = {b10, b11};
                mma16(sacc[ni], qf[kk], bf0);
                mma16(sacc[ni + 1], qf[kk], bf1);
            }
        }

        // online softmax over this 64-col block
        float mx0 = -1e30f, mx1 = -1e30f;
        #pragma unroll
        for (int ni = 0; ni < 8; ni++) {
            mx0 = fmaxf(mx0, fmaxf(sacc[ni][0], sacc[ni][1]));
            mx1 = fmaxf(mx1, fmaxf(sacc[ni][2], sacc[ni][3]));
        }
        mx0 = fmaxf(mx0, __shfl_xor_sync(0xFFFFFFFFu, mx0, 1));
        mx0 = fmaxf(mx0, __shfl_xor_sync(0xFFFFFFFFu, mx0, 2));
        mx1 = fmaxf(mx1, __shfl_xor_sync(0xFFFFFFFFu, mx1, 1));
        mx1 = fmaxf(mx1, __shfl_xor_sync(0xFFFFFFFFu, mx1, 2));
        const float mn0 = fmaxf(m0, mx0), mn1 = fmaxf(m1, mx1);
        const float al0 = expf(m0 - mn0), al1 = expf(m1 - mn1);

        float rs0 = 0.0f, rs1 = 0.0f;
        #pragma unroll
        for (int ni = 0; ni < 8; ni++) {
            float p0 = expf(sacc[ni][0] - mn0);
            float p1 = expf(sacc[ni][1] - mn0);
            float p2 = expf(sacc[ni][2] - mn1);
            float p3 = expf(sacc[ni][3] - mn1);
            rs0 += p0 + p1; rs1 += p2 + p3;
            const int col = ni * 8 + 2 * lc;
            *reinterpret_cast<__half2*>(pw + lr * FA_STR + col)       = __floats2half2_rn(p0, p1);
            *reinterpret_cast<__half2*>(pw + (lr + 8) * FA_STR + col) = __floats2half2_rn(p2, p3);
        }
        rs0 += __shfl_xor_sync(0xFFFFFFFFu, rs0, 1);
        rs0 += __shfl_xor_sync(0xFFFFFFFFu, rs0, 2);
        rs1 += __shfl_xor_sync(0xFFFFFFFFu, rs1, 1);
        rs1 += __shfl_xor_sync(0xFFFFFFFFu, rs1, 2);
        m0 = mn0; m1 = mn1;
        l0 = l0 * al0 + rs0;
        l1 = l1 * al1 + rs1;
        #pragma unroll
        for (int ni = 0; ni < 8; ni++) {
            oacc[ni][0] *= al0; oacc[ni][1] *= al0;
            oacc[ni][2] *= al1; oacc[ni][3] *= al1;
        }
        __syncwarp();

        // O += P V : P (16 x 64) A-operand; Vt smem [dh][s-slice] = B [n][k]
        #pragma unroll
        for (int kk2 = 0; kk2 < 4; kk2++) {
            uint32_t af[4];
            ldsm4(af[0], af[1], af[2], af[3],
                  smem_u32(pw + arow * FA_STR + kk2 * 16 + acol));
            #pragma unroll
            for (int ni = 0; ni < 8; ni += 2) {
                uint32_t b00, b01, b10, b11;
                ldsm4(b00, b01, b10, b11,
                      smem_u32(vs + (ni * 8 + brow) * FA_STR + kk2 * 16 + bcol));
                uint32_t bf0[2] = {b00, b01}, bf1[2] = {b10, b11};
                mma16(oacc[ni], af, bf0);
                mma16(oacc[ni + 1], af, bf1);
            }
        }
        __syncthreads();  // before next loadkv overwrites a stage
    }

    // epilogue: divide by l, write [B,S,D] half
    const float inv0 = 1.0f / l0, inv1 = 1.0f / l1;
    const int b = bh >> 3, h = bh & 7;
    const int r0 = qt * 128 + w * 16 + lr;
    #pragma unroll
    for (int ni = 0; ni < 8; ni++) {
        const int n = h * 64 + ni * 8 + 2 * lc;
        long o0 = ((long)(b * S_ + r0)) * D_ + n;
        long o1 = ((long)(b * S_ + r0 + 8)) * D_ + n;
        *reinterpret_cast<__half2*>(O + o0) = __floats2half2_rn(oacc[ni][0] * inv0, oacc[ni][1] * inv0);
        *reinterpret_cast<__half2*>(O + o1) = __floats2half2_rn(oacc[ni][2] * inv1, oacc[ni][3] * inv1);
    }
}

// ---------------------------------------------------------------------------
// Merged weight prep: transpose + fp16 convert all six weights in one launch.
// ---------------------------------------------------------------------------
__global__ __launch_bounds__(256) void prep_all(
    const float* __restrict__ wq, const float* __restrict__ wk,
    const float* __restrict__ wv, const float* __restrict__ wo,
    const float* __restrict__ w1, const float* __restrict__ w2,
    __half* __restrict__ out)
{
    __shared__ float t[32][33];
    const int id = blockIdx.x;
    const float* src; __half* dst; int K, N, ki, ni;
    if (id < 8192) {
        const int wsel = id >> 11, rem = id & 2047;
        const int layer = rem >> 8, tile = rem & 255;
        K = 512; N = 512; ki = tile >> 4; ni = tile & 15;
        src = (wsel == 0 ? wq : wsel == 1 ? wk : wsel == 2 ? wv : wo) + (long)layer * 262144;
        dst = out + (wsel < 3 ? OFF_TQKV + (long)layer * SZ_QKV + (long)wsel * 262144
                              : OFF_TO + (long)layer * SZ_O);
    } else if (id < 16384) {
        const int rem = id - 8192, layer = rem >> 10, tile = rem & 1023;
        K = 512; N = 2048; ki = tile >> 6; ni = tile & 63;
        src = w1 + (long)layer * 1048576;
        dst = out + OFF_T1 + (long)layer * SZ_1;
    } else {
        const int rem = id - 16384, layer = rem >> 10, tile = rem & 1023;
        K = 2048; N = 512; ki = tile >> 4; ni = tile & 15;
        src = w2 + (long)layer * 1048576;
        dst = out + OFF_T2 + (long)layer * SZ_2;
    }
    const int k0 = ki * 32, n0 = ni * 32;
    #pragma unroll
    for (int i = threadIdx.y; i < 32; i += 8)
        t[i][threadIdx.x] = src[(long)(k0 + i) * N + n0 + threadIdx.x];
    __syncthreads();
    #pragma unroll
    for (int i = threadIdx.y; i < 32; i += 8)
        dst[(long)(n0 + i) * K + k0 + threadIdx.x] = __float2half_rn(t[threadIdx.x][i]);
}

// copy x -> gx (fp32) and gxh (half)
__global__ __launch_bounds__(256) void copy_half(const float* __restrict__ x,
                                                 float* __restrict__ gx,
                                                 __half* __restrict__ gxh, int n4)
{
    int i = blockIdx.x * blockDim.x + threadIdx.x;
    int stride = gridDim.x * blockDim.x;
    for (; i < n4; i += stride) {
        float4 v = reinterpret_cast<const float4*>(x)[i];
        reinterpret_cast<float4*>(gx)[i] = v;
        reinterpret_cast<__half2*>(gxh)[2 * i]     = __floats2half2_rn(v.x, v.y);
        reinterpret_cast<__half2*>(gxh)[2 * i + 1] = __floats2half2_rn(v.z, v.w);
    }
}

// ---------------------------------------------------------------------------
// Row LayerNorm over 512 elements; fp32 out + half out_h.
// ---------------------------------------------------------------------------
__global__ __launch_bounds__(128) void ln_k(const float* __restrict__ in,
                                            const float* __restrict__ g,
                                            const float* __restrict__ be,
                                            float* __restrict__ out,
                                            __half* __restrict__ out_h)
{
    const int row = blockIdx.x;
    const int t = threadIdx.x;
    const float4 v = reinterpret_cast<const float4*>(in + (long)row * D_)[t];

    float s  = v.x + v.y + v.z + v.w;
    float sq = v.x * v.x + v.y * v.y + v.z * v.z + v.w * v.w;
    #pragma unroll
    for (int o = 16; o; o >>= 1) {
        s  += __shfl_xor_sync(0xFFFFFFFFu, s, o);
        sq += __shfl_xor_sync(0xFFFFFFFFu, sq, o);
    }
    __shared__ float sh0[4], sh1[4];
    if ((t & 31) == 0) { sh0[t >> 5] = s; sh1[t >> 5] = sq; }
    __syncthreads();
    s  = sh0[0] + sh0[1] + sh0[2] + sh0[3];
    sq = sh1[0] + sh1[1] + sh1[2] + sh1[3];

    const float mean = s * (1.0f / D_);
    const float var  = sq * (1.0f / D_) - mean * mean;
    const float inv  = rsqrtf(var + LN_EPS);

    const float4 gg = reinterpret_cast<const float4*>(g)[t];
    const float4 bb = reinterpret_cast<const float4*>(be)[t];
    float4 o4;
    o4.x = (v.x - mean) * inv * gg.x + bb.x;
    o4.y = (v.y - mean) * inv * gg.y + bb.y;
    o4.z = (v.z - mean) * inv * gg.z + bb.z;
    o4.w = (v.w - mean) * inv * gg.w + bb.w;
    reinterpret_cast<float4*>(out + (long)row * D_)[t] = o4;
    __half2* oh = reinterpret_cast<__half2*>(out_h + (long)row * D_);
    oh[2 * t]     = __floats2half2_rn(o4.x, o4.y);
    oh[2 * t + 1] = __floats2half2_rn(o4.z, o4.w);
}

// ---------------------------------------------------------------------------
// Host driver
// ---------------------------------------------------------------------------
extern "C" void kernel_launch(void* const* d_in, const int* in_sizes, int n_in,
                              void* d_out, int out_size)
{
    const float* x   = (const float*)d_in[0];
    const float* wq  = (const float*)d_in[1];
    const float* bq  = (const float*)d_in[2];
    const float* wk  = (const float*)d_in[3];
    const float* bk  = (const float*)d_in[4];
    const float* wv  = (const float*)d_in[5];
    const float* bv  = (const float*)d_in[6];
    const float* wo  = (const float*)d_in[7];
    const float* bo  = (const float*)d_in[8];
    const float* g1  = (const float*)d_in[9];
    const float* be1 = (const float*)d_in[10];
    const float* w1  = (const float*)d_in[11];
    const float* b1  = (const float*)d_in[12];
    const float* w2  = (const float*)d_in[13];
    const float* b2  = (const float*)d_in[14];
    const float* g2  = (const float*)d_in[15];
    const float* be2 = (const float*)d_in[16];

    float *gx, *gtmp;
    __half *gxh, *gqkv, *gattn, *gffn, *gwH;
    cudaGetSymbolAddress((void**)&gx,    g_x);
    cudaGetSymbolAddress((void**)&gxh,   g_xh);
    cudaGetSymbolAddress((void**)&gqkv,  g_qkv);
    cudaGetSymbolAddress((void**)&gattn, g_attn);
    cudaGetSymbolAddress((void**)&gtmp,  g_tmp);
    cudaGetSymbolAddress((void**)&gffn,  g_ffn);
    cudaGetSymbolAddress((void**)&gwH,   g_wH);

    constexpr int SM_BIG = smem_bytes<128, 128>();   // 61440
    constexpr int SM_SML = smem_bytes<128, 64>();    // 46080
    (void)cudaFuncSetAttribute(mma_gemm<128,128,M_QKV>,  cudaFuncAttributeMaxDynamicSharedMemorySize, SM_BIG);
    (void)cudaFuncSetAttribute(mma_gemm<128,64,M_RES>,   cudaFuncAttributeMaxDynamicSharedMemorySize, SM_SML);
    (void)cudaFuncSetAttribute(mma_gemm<128,128,M_GELU>, cudaFuncAttributeMaxDynamicSharedMemorySize, SM_BIG);
    (void)cudaFuncSetAttribute(flash_k, cudaFuncAttributeMaxDynamicSharedMemorySize, FA_SMEM);

    copy_half<<<512, 256>>>(x, gx, gxh, M_ROWS * D_ / 4);
    prep_all<<<24576, dim3(32, 8)>>>(wq, wk, wv, wo, w1, w2, gwH);

    const __half* gq  = gqkv;
    const __half* gk  = gqkv + MD;
    const __half* gvT = gqkv + 2 * MD;

    const dim3 gQKV(1536 / 128, M_ROWS / 128);   // (12, 32)
    const dim3 gOP(512 / 64, M_ROWS / 128);      // (8, 32) = 256 CTAs
    const dim3 gF1(2048 / 128, M_ROWS / 128);    // (16, 32)
    const dim3 gFA(S_ / 128, B_ * H_);           // (8, 32)

    for (int l = 0; l < L_; l++) {
        const __half* wqkvH_l = gwH + OFF_TQKV + (long)l * SZ_QKV;
        const __half* woH_l   = gwH + OFF_TO   + (long)l * SZ_O;
        const __half* w1H_l   = gwH + OFF_T1   + (long)l * SZ_1;
        const __half* w2H_l   = gwH + OFF_T2   + (long)l * SZ_2;
        const float* bq_l = bq + (long)l * D_;
        const float* bk_l = bk + (long)l * D_;
        const float* bv_l = bv + (long)l * D_;
        const float* bo_l = bo + (long)l * D_;
        const float* b1_l = b1 + (long)l * F_;
        const float* b2_l = b2 + (long)l * D_;
        const float* g1_l = g1 + (long)l * D_;
        const float* g2_l = g2 + (long)l * D_;
        const float* be1_l = be1 + (long)l * D_;
        const float* be2_l = be2 + (long)l * D_;

        // fused QKV projection -> q,k [B,H,S,DH], vT [B,H,DH,S] (half)
        mma_gemm<128,128,M_QKV><<<gQKV, 128, SM_BIG>>>(
            gxh, wqkvH_l, bq_l, bk_l, bv_l, nullptr, nullptr, gqkv, 1536, 512);

        // fused attention
        flash_k<<<gFA, 256, FA_SMEM>>>(gq, gk, gvT, gattn);

        // O projection + bias + residual (fp32 out), BN=64 for full-wave fill
        mma_gemm<128,64,M_RES><<<gOP, 128, SM_SML>>>(
            gattn, woH_l, bo_l, nullptr, nullptr, gx, gtmp, nullptr, 512, 512);
        ln_k<<<M_ROWS, 128>>>(gtmp, g1_l, be1_l, gx, gxh);

        // FFN1 + GELU (half out)
        mma_gemm<128,128,M_GELU><<<gF1, 128, SM_BIG>>>(
            gxh, w1H_l, b1_l, nullptr, nullptr, nullptr, nullptr, gffn, 2048, 512);
        // FFN2 + bias + residual (fp32 out), BN=64
        mma_gemm<128,64,M_RES><<<gOP, 128, SM_SML>>>(
            gffn, w2H_l, b2_l, nullptr, nullptr, gx, gtmp, nullptr, 512, 2048);
        ln_k<<<M_ROWS, 128>>>(gtmp, g2_l, be2_l,
                              (l == L_ - 1) ? (float*)d_out : gx, gxh);
    }
}